// round 5
// baseline (speedup 1.0000x reference)
#include <cuda_runtime.h>
#include <cuda_bf16.h>
#include <math.h>
#include <stdint.h>

#define NB 32
#define NC 1536
#define NN 1024
#define NHID 512
#define NL 128
#define NM 64
#define NG 256

// ---- smem tile geometry ----
#define APAD 40
#define BPAD 136
#define A_BYTES (128 * APAD * 2)
#define B_BYTES (32 * BPAD * 2)
#define STAGE_BYTES (2 * A_BYTES + 2 * B_BYTES)   // 37888
#define SMEM_TOTAL (3 * STAGE_BYTES)              // 113664 (3 stages)

// ---- scratch ----
__device__ __nv_bfloat16 g_xh[(size_t)NB * NC * NN];
__device__ __nv_bfloat16 g_xl[(size_t)NB * NC * NN];
__device__ __nv_bfloat16 g_hh[(size_t)NB * NHID * NN];
__device__ __nv_bfloat16 g_hl[(size_t)NB * NHID * NN];
__device__ __nv_bfloat16 g_fh[(size_t)NB * NL * NN];
__device__ __nv_bfloat16 g_fl[(size_t)NB * NL * NN];
__device__ __nv_bfloat16 g_fnj[(size_t)NB * NN * NL];
__device__ __nv_bfloat16 g_fnk[(size_t)NB * NL * NN];
__device__ float         g_p  [(size_t)NB * NM * NN];
__device__ __nv_bfloat16 g_Pth[(size_t)NB * NN * NM];
__device__ __nv_bfloat16 g_Ptl[(size_t)NB * NN * NM];
__device__ __nv_bfloat16 g_w1h[NHID * NC], g_w1l[NHID * NC];
__device__ __nv_bfloat16 g_w2h[NHID * NC], g_w2l[NHID * NC];
__device__ __nv_bfloat16 g_wch[NL * NHID], g_wcl[NL * NHID];
__device__ __nv_bfloat16 g_wsh[NM * NHID], g_wsl[NM * NHID];
__device__ float g_u[NB * (NM + 1)];
__device__ float g_v[NB * NN];
__device__ float g_norms[NB * NN];
__device__ float g_bw[NB * NN];
__device__ float g_agg[NB * NL * NM];
__device__ float g_tht[NB * NHID];
__device__ float g_tk[NB * NG];

__device__ __forceinline__ void split2(float v, __nv_bfloat16& h, __nv_bfloat16& l) {
    h = __float2bfloat16(v);
    l = __float2bfloat16(v - __bfloat162float(h));
}
__device__ __forceinline__ uint32_t smem_u32(const void* p) {
    uint32_t a;
    asm("{ .reg .u64 t; cvta.to.shared.u64 t, %1; cvt.u32.u64 %0, t; }" : "=r"(a) : "l"(p));
    return a;
}
__device__ __forceinline__ void cp16(uint32_t d, const void* s, bool pred) {
    int sz = pred ? 16 : 0;
    asm volatile("cp.async.cg.shared.global [%0], [%1], 16, %2;"
                 :: "r"(d), "l"(s), "r"(sz) : "memory");
}
#define CP_COMMIT() asm volatile("cp.async.commit_group;" ::: "memory")
#define CP_WAIT0()  asm volatile("cp.async.wait_group 0;" ::: "memory")
#define CP_WAIT1()  asm volatile("cp.async.wait_group 1;" ::: "memory")

__device__ __forceinline__ void ldmx4(uint32_t* r, uint32_t a) {
    asm volatile("ldmatrix.sync.aligned.m8n8.x4.shared.b16 {%0,%1,%2,%3}, [%4];"
        : "=r"(r[0]), "=r"(r[1]), "=r"(r[2]), "=r"(r[3]) : "r"(a));
}
__device__ __forceinline__ void ldmx2t(uint32_t* r, uint32_t a) {
    asm volatile("ldmatrix.sync.aligned.m8n8.x2.trans.shared.b16 {%0,%1}, [%2];"
        : "=r"(r[0]), "=r"(r[1]) : "r"(a));
}
__device__ __forceinline__ void mma16816(float* d, const uint32_t* a, const uint32_t* b) {
    asm volatile("mma.sync.aligned.m16n8k16.row.col.f32.bf16.bf16.f32 "
        "{%0,%1,%2,%3}, {%4,%5,%6,%7}, {%8,%9}, {%0,%1,%2,%3};"
        : "+f"(d[0]), "+f"(d[1]), "+f"(d[2]), "+f"(d[3])
        : "r"(a[0]), "r"(a[1]), "r"(a[2]), "r"(a[3]), "r"(b[0]), "r"(b[1]));
}

// ================= MMA GEMM (3-stage, full regs) =================
__global__ void __launch_bounds__(256, 1) mma_gemm_kernel(
    const __nv_bfloat16* __restrict__ Ah, const __nv_bfloat16* __restrict__ Al, long sA,
    const __nv_bfloat16* __restrict__ Bh, const __nv_bfloat16* __restrict__ Bl, long sB,
    int K, int ldB, int Mvalid, int Nvalid,
    const float* __restrict__ bias, int relu, int mode,
    __nv_bfloat16* __restrict__ o0, __nv_bfloat16* __restrict__ o1,
    float* __restrict__ of, long sO, int ldo,
    const float* __restrict__ pa, const float* __restrict__ pb)
{
    extern __shared__ char smem[];
    const uint32_t su = smem_u32(smem);
    const int tid = threadIdx.x, lane = tid & 31, wid = tid >> 5;
    const int wm = wid >> 2, wn = wid & 3;
    const int bz = blockIdx.z, n0 = blockIdx.x * 128, m0 = blockIdx.y * 128;
    const bool x3 = (Al != nullptr);

    const __nv_bfloat16* A_h = Ah + (long)bz * sA + (long)m0 * K;
    const __nv_bfloat16* A_l = x3 ? Al + (long)bz * sA + (long)m0 * K : A_h;
    const __nv_bfloat16* B_h = Bh + (long)bz * sB;
    const __nv_bfloat16* B_l = x3 ? Bl + (long)bz * sB : B_h;
    const int mMax = (Mvalid - m0 < 128) ? (Mvalid - m0) : 128;

    float acc[4][4][4];
#pragma unroll
    for (int i = 0; i < 4; i++)
#pragma unroll
        for (int j = 0; j < 4; j++)
#pragma unroll
            for (int q = 0; q < 4; q++) acc[i][j][q] = 0.f;

    const int nc = K >> 5;

    auto prefetch = [&](int c, int st) {
        uint32_t sa = su + st * STAGE_BYTES;
        long kb = (long)c * 32;
#pragma unroll
        for (int i = 0; i < 2; i++) {
            int idx = tid + i * 256;
            int row = idx >> 2, cc = idx & 3;
            uint32_t doff = sa + row * (APAD * 2) + cc * 16;
            bool p = row < mMax;
            cp16(doff, A_h + (long)row * K + kb + cc * 8, p);
            if (x3) cp16(doff + A_BYTES, A_l + (long)row * K + kb + cc * 8, p);
        }
#pragma unroll
        for (int i = 0; i < 2; i++) {
            int idx = tid + i * 256;
            int row = idx >> 4, cc = idx & 15;
            uint32_t doff = sa + 2 * A_BYTES + row * (BPAD * 2) + cc * 16;
            bool p = (n0 + cc * 8) < Nvalid;
            cp16(doff, B_h + (kb + row) * (long)ldB + n0 + cc * 8, p);
            if (x3) cp16(doff + B_BYTES, B_l + (kb + row) * (long)ldB + n0 + cc * 8, p);
        }
    };

    prefetch(0, 0);
    CP_COMMIT();
    if (nc > 1) { prefetch(1, 1); CP_COMMIT(); }

    for (int c = 0; c < nc; c++) {
        if (c + 1 < nc) CP_WAIT1(); else CP_WAIT0();
        __syncthreads();
        if (c + 2 < nc) { prefetch(c + 2, (c + 2) % 3); CP_COMMIT(); }

        uint32_t sa = su + (c % 3) * STAGE_BYTES;
#pragma unroll
        for (int kk = 0; kk < 2; kk++) {
            uint32_t afh[4][4], afl[4][4];
#pragma unroll
            for (int mi = 0; mi < 4; mi++) {
                uint32_t ad = sa + ((wm * 64 + mi * 16 + (lane & 15)) * APAD
                                    + kk * 16 + (lane >> 4) * 8) * 2;
                ldmx4(afh[mi], ad);
                if (x3) ldmx4(afl[mi], ad + A_BYTES);
            }
#pragma unroll
            for (int ni = 0; ni < 4; ni++) {
                uint32_t bd = sa + 2 * A_BYTES
                            + (kk * 16 + (lane & 15)) * (BPAD * 2)
                            + (wn * 32 + ni * 8) * 2;
                uint32_t bfh[2], bfl[2];
                ldmx2t(bfh, bd);
                if (x3) ldmx2t(bfl, bd + B_BYTES);
#pragma unroll
                for (int mi = 0; mi < 4; mi++) {
                    mma16816(acc[mi][ni], afh[mi], bfh);
                    if (x3) {
                        mma16816(acc[mi][ni], afh[mi], bfl);
                        mma16816(acc[mi][ni], afl[mi], bfh);
                    }
                }
            }
        }
    }

    const int g = lane >> 2, tq = lane & 3;
    if (mode == 2) {
        const float a = *pa, bb = *pb;
        const bool fast = (fabsf(a) + fabsf(bb)) <= 1.0f;
#pragma unroll
        for (int mi = 0; mi < 4; mi++) {
            float r0 = 0.f, r1 = 0.f;
#pragma unroll
            for (int ni = 0; ni < 4; ni++) {
#pragma unroll
                for (int q = 0; q < 4; q++) {
                    float z = a * acc[mi][ni][q] + bb;
                    float s;
                    if (fast) {
                        float tt = 0.5f * z, t2 = tt * tt;
                        float th = tt * (1.f + t2 * (-0.3333333333f
                                   + t2 * (0.1333333333f - t2 * 0.05396825397f)));
                        s = 0.5f + 0.5f * th;
                    } else {
                        s = 1.f / (1.f + __expf(-z));
                    }
                    if (q < 2) r0 += s; else r1 += s;
                }
            }
            r0 += __shfl_xor_sync(0xffffffffu, r0, 1);
            r0 += __shfl_xor_sync(0xffffffffu, r0, 2);
            r1 += __shfl_xor_sync(0xffffffffu, r1, 1);
            r1 += __shfl_xor_sync(0xffffffffu, r1, 2);
            if (tq == 0) {
                int j = m0 + wm * 64 + mi * 16 + g;
                atomicAdd(&g_bw[bz * NN + j], r0);
                atomicAdd(&g_bw[bz * NN + j + 8], r1);
            }
        }
        return;
    }

#pragma unroll
    for (int mi = 0; mi < 4; mi++) {
        int r0 = m0 + wm * 64 + mi * 16 + g;
        int r1 = r0 + 8;
        float b0v = (bias && r0 < Mvalid) ? bias[r0] : 0.f;
        float b1v = (bias && r1 < Mvalid) ? bias[r1] : 0.f;
#pragma unroll
        for (int ni = 0; ni < 4; ni++) {
            int col = n0 + wn * 32 + ni * 8 + tq * 2;
            if (col >= Nvalid) continue;
            float v00 = acc[mi][ni][0] + b0v, v01 = acc[mi][ni][1] + b0v;
            float v10 = acc[mi][ni][2] + b1v, v11 = acc[mi][ni][3] + b1v;
            if (relu) {
                v00 = fmaxf(v00, 0.f); v01 = fmaxf(v01, 0.f);
                v10 = fmaxf(v10, 0.f); v11 = fmaxf(v11, 0.f);
            }
            if (mode == 0) {
                if (r0 < Mvalid) {
                    long off = (long)bz * sO + (long)r0 * ldo + col;
                    __nv_bfloat16 h0, l0, h1, l1;
                    split2(v00, h0, l0); split2(v01, h1, l1);
                    *reinterpret_cast<uint32_t*>(o0 + off) =
                        (uint32_t)__bfloat16_as_ushort(h0) | ((uint32_t)__bfloat16_as_ushort(h1) << 16);
                    *reinterpret_cast<uint32_t*>(o1 + off) =
                        (uint32_t)__bfloat16_as_ushort(l0) | ((uint32_t)__bfloat16_as_ushort(l1) << 16);
                }
                if (r1 < Mvalid) {
                    long off = (long)bz * sO + (long)r1 * ldo + col;
                    __nv_bfloat16 h0, l0, h1, l1;
                    split2(v10, h0, l0); split2(v11, h1, l1);
                    *reinterpret_cast<uint32_t*>(o0 + off) =
                        (uint32_t)__bfloat16_as_ushort(h0) | ((uint32_t)__bfloat16_as_ushort(h1) << 16);
                    *reinterpret_cast<uint32_t*>(o1 + off) =
                        (uint32_t)__bfloat16_as_ushort(l0) | ((uint32_t)__bfloat16_as_ushort(l1) << 16);
                }
            } else {
                if (r0 < Mvalid)
                    *reinterpret_cast<float2*>(of + (long)bz * sO + (long)r0 * ldo + col) =
                        make_float2(v00, v01);
                if (r1 < Mvalid)
                    *reinterpret_cast<float2*>(of + (long)bz * sO + (long)r1 * ldo + col) =
                        make_float2(v10, v11);
            }
        }
    }
}

// ============ conversions ============
__global__ void convw_kernel(const float* __restrict__ s, __nv_bfloat16* __restrict__ dh,
                             __nv_bfloat16* __restrict__ dl, int count)
{
    for (int i = blockIdx.x * blockDim.x + threadIdx.x; i < count; i += gridDim.x * blockDim.x) {
        __nv_bfloat16 h, l; split2(s[i], h, l);
        dh[i] = h; dl[i] = l;
    }
}
__global__ void convx_kernel(const float* __restrict__ x)
{
    long i = (long)blockIdx.x * blockDim.x + threadIdx.x;
    const long total = (long)NB * NC * NN;
    for (; i < total; i += (long)gridDim.x * blockDim.x) {
        __nv_bfloat16 h, l; split2(x[i], h, l);
        g_xh[i] = h; g_xl[i] = l;
    }
}

// ============ token MLP ============
__global__ void tk1_kernel(const float* __restrict__ t, const float* __restrict__ W,
                           const float* __restrict__ bias)
{
    int gw = (blockIdx.x * blockDim.x + threadIdx.x) >> 5;
    int lane = threadIdx.x & 31;
    int o = gw % NHID, b = gw / NHID;
    const float* tr = t + (long)b * NC;
    const float* wr = W + (long)o * NC;
    float s = 0.f;
    for (int k = lane; k < NC; k += 32) s = fmaf(tr[k], wr[k], s);
#pragma unroll
    for (int off = 16; off > 0; off >>= 1) s += __shfl_xor_sync(0xffffffffu, s, off);
    if (lane == 0) g_tht[b * NHID + o] = fmaxf(s + bias[o], 0.f);
}
__global__ void tk2_kernel(const float* __restrict__ W, const float* __restrict__ bias)
{
    int gw = (blockIdx.x * blockDim.x + threadIdx.x) >> 5;
    int lane = threadIdx.x & 31;
    int o = gw % NG, b = gw / NG;
    const float* hr = g_tht + (long)b * NHID;
    const float* wr = W + (long)o * NHID;
    float s = 0.f;
    for (int k = lane; k < NHID; k += 32) s = fmaf(hr[k], wr[k], s);
#pragma unroll
    for (int off = 16; off > 0; off >>= 1) s += __shfl_xor_sync(0xffffffffu, s, off);
    if (lane == 0) g_tk[b * NG + o] = s + bias[o];
}

// ============ column norms of f ============
__global__ void colnorm_kernel()
{
    int idx = blockIdx.x * blockDim.x + threadIdx.x;
    if (idx >= NB * NN) return;
    int b = idx >> 10, j = idx & (NN - 1);
    long base = (long)b * NL * NN + j;
    float s = 0.f;
    for (int l = 0; l < NL; l++) {
        float v = __bfloat162float(g_fh[base + (long)l * NN]) +
                  __bfloat162float(g_fl[base + (long)l * NN]);
        s = fmaf(v, v, s);
    }
    g_norms[idx] = fmaxf(sqrtf(s), 1e-12f);
}

// ============ fn: [l][n] and transposed [n][l] ============
__global__ void fnt_kernel()
{
    __shared__ float tile[32][33];
    int b = blockIdx.z, l0 = blockIdx.y * 32, n0 = blockIdx.x * 32;
    int tx = threadIdx.x, ty = threadIdx.y;
    long fb = (long)b * NL * NN;
#pragma unroll
    for (int i = 0; i < 4; i++) {
        int l = l0 + ty + i * 8;
        long off = fb + (long)l * NN + n0 + tx;
        tile[ty + i * 8][tx] = __bfloat162float(g_fh[off]) + __bfloat162float(g_fl[off]);
    }
    __syncthreads();
    float nv = g_norms[b * NN + n0 + tx];
#pragma unroll
    for (int i = 0; i < 4; i++) {
        int l = l0 + ty + i * 8;
        g_fnk[fb + (long)l * NN + n0 + tx] = __float2bfloat16(tile[ty + i * 8][tx] / nv);
    }
#pragma unroll
    for (int i = 0; i < 4; i++) {
        int r = ty + i * 8;
        float nv2 = g_norms[b * NN + n0 + r];
        g_fnj[((long)b * NN + n0 + r) * NL + l0 + tx] =
            __float2bfloat16(tile[tx][r] / nv2);
    }
}

// ============ Sinkhorn, split into parallel u/v kernels ============
// u-update: one warp per (b,i), i in [0,65)
__global__ void sk_u_kernel(const float* __restrict__ pdust)
{
    const float NORMC = -logf((float)(NM + NN));
    const float LOGN = logf((float)NN);
    int gw = (blockIdx.x * blockDim.x + threadIdx.x) >> 5;
    int lane = threadIdx.x & 31;
    if (gw >= NB * (NM + 1)) return;
    int i = gw % (NM + 1), b = gw / (NM + 1);

    const float4* v4 = reinterpret_cast<const float4*>(g_v + b * NN);
    float xs[32];
    if (i < NM) {
        const float4* p4 = reinterpret_cast<const float4*>(g_p + ((long)b * NM + i) * NN);
#pragma unroll
        for (int w = 0; w < 8; w++) {
            float4 pv = p4[w * 32 + lane];
            float4 vv = v4[w * 32 + lane];
            xs[4*w]   = pv.x + vv.x; xs[4*w+1] = pv.y + vv.y;
            xs[4*w+2] = pv.z + vv.z; xs[4*w+3] = pv.w + vv.w;
        }
    } else {
        float dust = *pdust;
#pragma unroll
        for (int w = 0; w < 8; w++) {
            float4 vv = v4[w * 32 + lane];
            xs[4*w]   = dust + vv.x; xs[4*w+1] = dust + vv.y;
            xs[4*w+2] = dust + vv.z; xs[4*w+3] = dust + vv.w;
        }
    }
    float mx = xs[0];
#pragma unroll
    for (int q = 1; q < 32; q++) mx = fmaxf(mx, xs[q]);
#pragma unroll
    for (int off = 16; off > 0; off >>= 1) mx = fmaxf(mx, __shfl_xor_sync(0xffffffffu, mx, off));
    float s = 0.f;
#pragma unroll
    for (int q = 0; q < 32; q++) s += __expf(xs[q] - mx);
#pragma unroll
    for (int off = 16; off > 0; off >>= 1) s += __shfl_xor_sync(0xffffffffu, s, off);
    if (lane == 0)
        g_u[b * (NM + 1) + i] = ((i < NM) ? NORMC : (LOGN + NORMC)) - (mx + __logf(s));
}

// v-update: one thread per (b,j); block handles 256 consecutive j of one batch
__global__ void sk_v_kernel(const float* __restrict__ pdust)
{
    const float NORMC = -logf((float)(NM + NN));
    __shared__ float su[NM + 1];
    int b = blockIdx.x >> 2, q = blockIdx.x & 3;
    int tid = threadIdx.x;
    if (tid <= NM) su[tid] = g_u[b * (NM + 1) + tid];
    __syncthreads();
    int j = q * 256 + tid;
    const float* pb = g_p + (long)b * NM * NN + j;
    float mx = *pdust + su[NM];
    float s = 1.f;
#pragma unroll 8
    for (int i = 0; i < NM; i++) {
        float x = pb[(long)i * NN] + su[i];
        if (x > mx) { s = s * __expf(mx - x) + 1.f; mx = x; }
        else        { s += __expf(x - mx); }
    }
    g_v[b * NN + j] = NORMC - (mx + __logf(s));
}

// ============ column term: v <- v - NORM - pw*log(bw) ============
__global__ void cterm_kernel(const float* __restrict__ pbp)
{
    const float NORMC = -logf((float)(NM + NN));
    int idx = blockIdx.x * blockDim.x + threadIdx.x;
    if (idx >= NB * NN) return;
    g_v[idx] = g_v[idx] - NORMC - (*pbp) * __logf(g_bw[idx]);
}

// ============ P finalize -> P^T split bf16 [b][n][m] ============
__global__ void pfinal_kernel()
{
    long idx = (long)blockIdx.x * blockDim.x + threadIdx.x;
    int b = (int)(idx >> 16);
    int i = (int)((idx >> 10) & 63);
    int j = (int)(idx & 1023);
    float val = __expf(g_p[idx] + g_u[b * (NM + 1) + i] + g_v[b * NN + j]);
    __nv_bfloat16 h, l; split2(val, h, l);
    long o = ((long)b * NN + j) * NM + i;
    g_Pth[o] = h; g_Ptl[o] = l;
}

// ============ final normalize + concat ============
__global__ void final_kernel(float* __restrict__ out)
{
    const int b = blockIdx.x, tid = threadIdx.x;
    __shared__ float sred[256];
    __shared__ float cnorm[NM];
    __shared__ float stk, stot;

    float v = g_tk[b * NG + tid];
    sred[tid] = v * v;
    __syncthreads();
    for (int s = 128; s > 0; s >>= 1) { if (tid < s) sred[tid] += sred[tid + s]; __syncthreads(); }
    if (tid == 0) stk = fmaxf(sqrtf(sred[0]), 1e-12f);
    __syncthreads();
    {
        int m = tid & 63, part = tid >> 6;
        const float* ab = g_agg + (long)b * NL * NM;
        float s = 0.f;
        for (int l = part * 32; l < part * 32 + 32; l++) {
            float x = ab[(long)l * NM + m];
            s = fmaf(x, x, s);
        }
        sred[tid] = s;
        __syncthreads();
        if (tid < 64)
            cnorm[tid] = fmaxf(sqrtf(sred[tid] + sred[tid+64] + sred[tid+128] + sred[tid+192]), 1e-12f);
        __syncthreads();
    }
    const int ROW = NG + NL * NM;
    float* orow = out + (long)b * ROW;
    float tot = 0.f;
    for (int idx = tid; idx < ROW; idx += 256) {
        float val;
        if (idx < NG) val = g_tk[b * NG + idx] / stk;
        else {
            int r = idx - NG;
            val = g_agg[((long)b * NL + (r >> 6)) * NM + (r & 63)] / cnorm[r & 63];
        }
        orow[idx] = val;
        tot += val * val;
    }
    sred[tid] = tot;
    __syncthreads();
    for (int s = 128; s > 0; s >>= 1) { if (tid < s) sred[tid] += sred[tid + s]; __syncthreads(); }
    if (tid == 0) stot = fmaxf(sqrtf(sred[0]), 1e-12f);
    __syncthreads();
    for (int idx = tid; idx < ROW; idx += 256) orow[idx] /= stot;
}

// ============ launcher ============
extern "C" void kernel_launch(void* const* d_in, const int* in_sizes, int n_in,
                              void* d_out, int out_size)
{
    (void)in_sizes; (void)n_in; (void)out_size;
    const float* x    = (const float*)d_in[0];
    const float* t    = (const float*)d_in[1];
    const float* Wc1  = (const float*)d_in[2];
    const float* bc1  = (const float*)d_in[3];
    const float* Wc2  = (const float*)d_in[4];
    const float* bc2  = (const float*)d_in[5];
    const float* Ws1  = (const float*)d_in[6];
    const float* bs1  = (const float*)d_in[7];
    const float* Ws2  = (const float*)d_in[8];
    const float* bs2  = (const float*)d_in[9];
    const float* Wt1  = (const float*)d_in[10];
    const float* bt1  = (const float*)d_in[11];
    const float* Wt2  = (const float*)d_in[12];
    const float* bt2  = (const float*)d_in[13];
    const float* dust = (const float*)d_in[14];
    const float* ba   = (const float*)d_in[15];
    const float* bbp  = (const float*)d_in[16];
    const float* bp   = (const float*)d_in[17];
    float* out = (float*)d_out;

    __nv_bfloat16 *xh, *xl, *hh, *hl, *fh, *fl, *fnj, *fnk, *Pth, *Ptl;
    __nv_bfloat16 *w1h, *w1l, *w2h, *w2l, *wch, *wcl, *wsh, *wsl;
    float *pp, *pbw, *pagg, *pv;
    cudaGetSymbolAddress((void**)&xh, g_xh);   cudaGetSymbolAddress((void**)&xl, g_xl);
    cudaGetSymbolAddress((void**)&hh, g_hh);   cudaGetSymbolAddress((void**)&hl, g_hl);
    cudaGetSymbolAddress((void**)&fh, g_fh);   cudaGetSymbolAddress((void**)&fl, g_fl);
    cudaGetSymbolAddress((void**)&fnj, g_fnj); cudaGetSymbolAddress((void**)&fnk, g_fnk);
    cudaGetSymbolAddress((void**)&Pth, g_Pth); cudaGetSymbolAddress((void**)&Ptl, g_Ptl);
    cudaGetSymbolAddress((void**)&w1h, g_w1h); cudaGetSymbolAddress((void**)&w1l, g_w1l);
    cudaGetSymbolAddress((void**)&w2h, g_w2h); cudaGetSymbolAddress((void**)&w2l, g_w2l);
    cudaGetSymbolAddress((void**)&wch, g_wch); cudaGetSymbolAddress((void**)&wcl, g_wcl);
    cudaGetSymbolAddress((void**)&wsh, g_wsh); cudaGetSymbolAddress((void**)&wsl, g_wsl);
    cudaGetSymbolAddress((void**)&pp, g_p);    cudaGetSymbolAddress((void**)&pbw, g_bw);
    cudaGetSymbolAddress((void**)&pagg, g_agg);
    cudaGetSymbolAddress((void**)&pv, g_v);

    cudaFuncSetAttribute(mma_gemm_kernel, cudaFuncAttributeMaxDynamicSharedMemorySize, SMEM_TOTAL);

    // splits
    convw_kernel<<<256, 256>>>(Wc1, w1h, w1l, NHID * NC);
    convw_kernel<<<256, 256>>>(Ws1, w2h, w2l, NHID * NC);
    convw_kernel<<<64, 256>>>(Wc2, wch, wcl, NL * NHID);
    convw_kernel<<<32, 256>>>(Ws2, wsh, wsl, NM * NHID);
    convx_kernel<<<8192, 256>>>(x);

    // token MLP
    tk1_kernel<<<(NB * NHID * 32) / 256, 256>>>(t, Wt1, bt1);
    tk2_kernel<<<(NB * NG * 32) / 256, 256>>>(Wt2, bt2);

    // conv stacks
    mma_gemm_kernel<<<dim3(NN/128, NHID/128, NB), 256, SMEM_TOTAL>>>(
        w1h, w1l, 0, xh, xl, (long)NC * NN,
        NC, NN, NHID, NN, bc1, 1, 0, hh, hl, nullptr, (long)NHID * NN, NN, nullptr, nullptr);
    mma_gemm_kernel<<<dim3(NN/128, 1, NB), 256, SMEM_TOTAL>>>(
        wch, wcl, 0, hh, hl, (long)NHID * NN,
        NHID, NN, NL, NN, bc2, 0, 0, fh, fl, nullptr, (long)NL * NN, NN, nullptr, nullptr);
    mma_gemm_kernel<<<dim3(NN/128, NHID/128, NB), 256, SMEM_TOTAL>>>(
        w2h, w2l, 0, xh, xl, (long)NC * NN,
        NC, NN, NHID, NN, bs1, 1, 0, hh, hl, nullptr, (long)NHID * NN, NN, nullptr, nullptr);
    mma_gemm_kernel<<<dim3(NN/128, 1, NB), 256, SMEM_TOTAL>>>(
        wsh, wsl, 0, hh, hl, (long)NHID * NN,
        NHID, NN, NM, NN, bs2, 0, 1, nullptr, nullptr, pp, (long)NM * NN, NN, nullptr, nullptr);

    // burst reweighting
    colnorm_kernel<<<(NB * NN) / 256, 256>>>();
    fnt_kernel<<<dim3(NN/32, NL/32, NB), dim3(32, 8)>>>();
    cudaMemsetAsync(pbw, 0, (size_t)NB * NN * sizeof(float));
    mma_gemm_kernel<<<dim3(NN/128, NN/128, NB), 256, SMEM_TOTAL>>>(
        fnj, nullptr, (long)NN * NL, fnk, nullptr, (long)NL * NN,
        NL, NN, NN, NN, nullptr, 0, 2, nullptr, nullptr, nullptr, 0, 0, ba, bbp);

    // Sinkhorn: v=0; 3x (u-update, v-update) as parallel launches
    cudaMemsetAsync(pv, 0, (size_t)NB * NN * sizeof(float));
    for (int it = 0; it < 3; it++) {
        sk_u_kernel<<<(NB * (NM + 1) * 32 + 255) / 256, 256>>>(dust);
        sk_v_kernel<<<NB * 4, 256>>>(dust);
    }
    cterm_kernel<<<(NB * NN) / 256, 256>>>(bp);
    pfinal_kernel<<<(NB * NM * NN) / 256, 256>>>();

    // agg
    mma_gemm_kernel<<<dim3(1, 1, NB), 256, SMEM_TOTAL>>>(
        fh, fl, (long)NL * NN, Pth, Ptl, (long)NN * NM,
        NN, NM, NL, NM, nullptr, 0, 1, nullptr, nullptr, pagg, (long)NL * NM, NM, nullptr, nullptr);

    final_kernel<<<NB, 256>>>(out);
}

// round 6
// speedup vs baseline: 1.2645x; 1.2645x over previous
#include <cuda_runtime.h>
#include <cuda_bf16.h>
#include <math.h>
#include <stdint.h>

#define NB 32
#define NC 1536
#define NN 1024
#define NHID 512
#define NL 128
#define NM 64
#define NG 256

// ---- smem tile geometry ----
#define APAD 40
#define BPAD 136
#define A_BYTES (128 * APAD * 2)
#define B_BYTES (32 * BPAD * 2)
#define STAGE_BYTES (2 * A_BYTES + 2 * B_BYTES)   // 37888
#define SMEM_TOTAL (2 * STAGE_BYTES)              // 75776 (2 stages)

// ---- scratch ----
__device__ __nv_bfloat16 g_xh[(size_t)NB * NC * NN];
__device__ __nv_bfloat16 g_xl[(size_t)NB * NC * NN];
__device__ __nv_bfloat16 g_hh[(size_t)NB * NHID * NN];
__device__ __nv_bfloat16 g_hl[(size_t)NB * NHID * NN];
__device__ __nv_bfloat16 g_fh[(size_t)NB * NL * NN];
__device__ __nv_bfloat16 g_fl[(size_t)NB * NL * NN];
__device__ __nv_bfloat16 g_fnj[(size_t)NB * NN * NL];
__device__ __nv_bfloat16 g_fnk[(size_t)NB * NL * NN];
__device__ float         g_p  [(size_t)NB * NM * NN];
__device__ __nv_bfloat16 g_Pth[(size_t)NB * NN * NM];
__device__ __nv_bfloat16 g_Ptl[(size_t)NB * NN * NM];
__device__ __nv_bfloat16 g_w1h[NHID * NC], g_w1l[NHID * NC];
__device__ __nv_bfloat16 g_w2h[NHID * NC], g_w2l[NHID * NC];
__device__ __nv_bfloat16 g_wch[NL * NHID], g_wcl[NL * NHID];
__device__ __nv_bfloat16 g_wsh[NM * NHID], g_wsl[NM * NHID];
__device__ float g_u[NB * (NM + 1)];
__device__ float g_v[NB * NN];
__device__ float g_norms[NB * NN];
__device__ float g_bw[NB * NN];
__device__ float g_agg[NB * NL * NM];
__device__ float g_tht[NB * NHID];
__device__ float g_tk[NB * NG];

__device__ __forceinline__ void split2(float v, __nv_bfloat16& h, __nv_bfloat16& l) {
    h = __float2bfloat16(v);
    l = __float2bfloat16(v - __bfloat162float(h));
}
__device__ __forceinline__ uint32_t smem_u32(const void* p) {
    uint32_t a;
    asm("{ .reg .u64 t; cvta.to.shared.u64 t, %1; cvt.u32.u64 %0, t; }" : "=r"(a) : "l"(p));
    return a;
}
__device__ __forceinline__ void cp16(uint32_t d, const void* s, bool pred) {
    int sz = pred ? 16 : 0;
    asm volatile("cp.async.cg.shared.global [%0], [%1], 16, %2;"
                 :: "r"(d), "l"(s), "r"(sz) : "memory");
}
#define CP_COMMIT() asm volatile("cp.async.commit_group;" ::: "memory")
#define CP_WAIT0()  asm volatile("cp.async.wait_group 0;" ::: "memory")

__device__ __forceinline__ void ldmx4(uint32_t* r, uint32_t a) {
    asm volatile("ldmatrix.sync.aligned.m8n8.x4.shared.b16 {%0,%1,%2,%3}, [%4];"
        : "=r"(r[0]), "=r"(r[1]), "=r"(r[2]), "=r"(r[3]) : "r"(a));
}
__device__ __forceinline__ void ldmx2t(uint32_t* r, uint32_t a) {
    asm volatile("ldmatrix.sync.aligned.m8n8.x2.trans.shared.b16 {%0,%1}, [%2];"
        : "=r"(r[0]), "=r"(r[1]) : "r"(a));
}
__device__ __forceinline__ void mma16816(float* d, const uint32_t* a, const uint32_t* b) {
    asm volatile("mma.sync.aligned.m16n8k16.row.col.f32.bf16.bf16.f32 "
        "{%0,%1,%2,%3}, {%4,%5,%6,%7}, {%8,%9}, {%0,%1,%2,%3};"
        : "+f"(d[0]), "+f"(d[1]), "+f"(d[2]), "+f"(d[3])
        : "r"(a[0]), "r"(a[1]), "r"(a[2]), "r"(a[3]), "r"(b[0]), "r"(b[1]));
}

// ================= MMA GEMM (2-stage, pass-reordered split MMAs) =================
__global__ void __launch_bounds__(256, 2) mma_gemm_kernel(
    const __nv_bfloat16* __restrict__ Ah, const __nv_bfloat16* __restrict__ Al, long sA,
    const __nv_bfloat16* __restrict__ Bh, const __nv_bfloat16* __restrict__ Bl, long sB,
    int K, int ldB, int Mvalid, int Nvalid,
    const float* __restrict__ bias, int relu, int mode,
    __nv_bfloat16* __restrict__ o0, __nv_bfloat16* __restrict__ o1,
    float* __restrict__ of, long sO, int ldo,
    const float* __restrict__ pa, const float* __restrict__ pb)
{
    extern __shared__ char smem[];
    const uint32_t su = smem_u32(smem);
    const int tid = threadIdx.x, lane = tid & 31, wid = tid >> 5;
    const int wm = wid >> 2, wn = wid & 3;
    const int bz = blockIdx.z, n0 = blockIdx.x * 128, m0 = blockIdx.y * 128;
    const bool x3 = (Al != nullptr);

    const __nv_bfloat16* A_h = Ah + (long)bz * sA + (long)m0 * K;
    const __nv_bfloat16* A_l = x3 ? Al + (long)bz * sA + (long)m0 * K : A_h;
    const __nv_bfloat16* B_h = Bh + (long)bz * sB;
    const __nv_bfloat16* B_l = x3 ? Bl + (long)bz * sB : B_h;
    const int mMax = (Mvalid - m0 < 128) ? (Mvalid - m0) : 128;

    float acc[4][4][4];
#pragma unroll
    for (int i = 0; i < 4; i++)
#pragma unroll
        for (int j = 0; j < 4; j++)
#pragma unroll
            for (int q = 0; q < 4; q++) acc[i][j][q] = 0.f;

    const int nc = K >> 5;

    auto prefetch = [&](int c, int st) {
        uint32_t sa = su + st * STAGE_BYTES;
        long kb = (long)c * 32;
#pragma unroll
        for (int i = 0; i < 2; i++) {
            int idx = tid + i * 256;
            int row = idx >> 2, cc = idx & 3;
            uint32_t doff = sa + row * (APAD * 2) + cc * 16;
            bool p = row < mMax;
            cp16(doff, A_h + (long)row * K + kb + cc * 8, p);
            if (x3) cp16(doff + A_BYTES, A_l + (long)row * K + kb + cc * 8, p);
        }
#pragma unroll
        for (int i = 0; i < 2; i++) {
            int idx = tid + i * 256;
            int row = idx >> 4, cc = idx & 15;
            uint32_t doff = sa + 2 * A_BYTES + row * (BPAD * 2) + cc * 16;
            bool p = (n0 + cc * 8) < Nvalid;
            cp16(doff, B_h + (kb + row) * (long)ldB + n0 + cc * 8, p);
            if (x3) cp16(doff + B_BYTES, B_l + (kb + row) * (long)ldB + n0 + cc * 8, p);
        }
    };

    prefetch(0, 0);
    CP_COMMIT();

    for (int c = 0; c < nc; c++) {
        CP_WAIT0();
        __syncthreads();
        if (c + 1 < nc) { prefetch(c + 1, (c + 1) & 1); CP_COMMIT(); }

        uint32_t sa = su + (c & 1) * STAGE_BYTES;
#pragma unroll
        for (int kk = 0; kk < 2; kk++) {
            // A fragments (hi + lo), cached for all three passes
            uint32_t afh[4][4], afl[4][4];
#pragma unroll
            for (int mi = 0; mi < 4; mi++) {
                uint32_t ad = sa + ((wm * 64 + mi * 16 + (lane & 15)) * APAD
                                    + kk * 16 + (lane >> 4) * 8) * 2;
                ldmx4(afh[mi], ad);
                if (x3) ldmx4(afl[mi], ad + A_BYTES);
            }
            // B-hi fragments, cached (used in passes hh and lh)
            uint32_t bfh[4][2];
#pragma unroll
            for (int ni = 0; ni < 4; ni++) {
                uint32_t bd = sa + 2 * A_BYTES
                            + (kk * 16 + (lane & 15)) * (BPAD * 2)
                            + (wn * 32 + ni * 8) * 2;
                ldmx2t(bfh[ni], bd);
            }
            // pass 1: hh — 16 independent MMAs
#pragma unroll
            for (int ni = 0; ni < 4; ni++)
#pragma unroll
                for (int mi = 0; mi < 4; mi++)
                    mma16816(acc[mi][ni], afh[mi], bfh[ni]);
            if (x3) {
                // pass 2: hi-A x lo-B (reload B-lo per ni; 2 live regs)
#pragma unroll
                for (int ni = 0; ni < 4; ni++) {
                    uint32_t bd = sa + 2 * A_BYTES + B_BYTES
                                + (kk * 16 + (lane & 15)) * (BPAD * 2)
                                + (wn * 32 + ni * 8) * 2;
                    uint32_t bfl[2];
                    ldmx2t(bfl, bd);
#pragma unroll
                    for (int mi = 0; mi < 4; mi++)
                        mma16816(acc[mi][ni], afh[mi], bfl);
                }
                // pass 3: lo-A x hi-B
#pragma unroll
                for (int ni = 0; ni < 4; ni++)
#pragma unroll
                    for (int mi = 0; mi < 4; mi++)
                        mma16816(acc[mi][ni], afl[mi], bfh[ni]);
            }
        }
    }

    const int g = lane >> 2, tq = lane & 3;
    if (mode == 2) {
        const float a = *pa, bb = *pb;
        const bool fast = (fabsf(a) + fabsf(bb)) <= 1.0f;
#pragma unroll
        for (int mi = 0; mi < 4; mi++) {
            float r0 = 0.f, r1 = 0.f;
#pragma unroll
            for (int ni = 0; ni < 4; ni++) {
#pragma unroll
                for (int q = 0; q < 4; q++) {
                    float z = a * acc[mi][ni][q] + bb;
                    float s;
                    if (fast) {
                        float tt = 0.5f * z, t2 = tt * tt;
                        float th = tt * (1.f + t2 * (-0.3333333333f
                                   + t2 * (0.1333333333f - t2 * 0.05396825397f)));
                        s = 0.5f + 0.5f * th;
                    } else {
                        s = 1.f / (1.f + __expf(-z));
                    }
                    if (q < 2) r0 += s; else r1 += s;
                }
            }
            r0 += __shfl_xor_sync(0xffffffffu, r0, 1);
            r0 += __shfl_xor_sync(0xffffffffu, r0, 2);
            r1 += __shfl_xor_sync(0xffffffffu, r1, 1);
            r1 += __shfl_xor_sync(0xffffffffu, r1, 2);
            if (tq == 0) {
                int j = m0 + wm * 64 + mi * 16 + g;
                atomicAdd(&g_bw[bz * NN + j], r0);
                atomicAdd(&g_bw[bz * NN + j + 8], r1);
            }
        }
        return;
    }

#pragma unroll
    for (int mi = 0; mi < 4; mi++) {
        int r0 = m0 + wm * 64 + mi * 16 + g;
        int r1 = r0 + 8;
        float b0v = (bias && r0 < Mvalid) ? bias[r0] : 0.f;
        float b1v = (bias && r1 < Mvalid) ? bias[r1] : 0.f;
#pragma unroll
        for (int ni = 0; ni < 4; ni++) {
            int col = n0 + wn * 32 + ni * 8 + tq * 2;
            if (col >= Nvalid) continue;
            float v00 = acc[mi][ni][0] + b0v, v01 = acc[mi][ni][1] + b0v;
            float v10 = acc[mi][ni][2] + b1v, v11 = acc[mi][ni][3] + b1v;
            if (relu) {
                v00 = fmaxf(v00, 0.f); v01 = fmaxf(v01, 0.f);
                v10 = fmaxf(v10, 0.f); v11 = fmaxf(v11, 0.f);
            }
            if (mode == 0) {
                if (r0 < Mvalid) {
                    long off = (long)bz * sO + (long)r0 * ldo + col;
                    __nv_bfloat16 h0, l0, h1, l1;
                    split2(v00, h0, l0); split2(v01, h1, l1);
                    *reinterpret_cast<uint32_t*>(o0 + off) =
                        (uint32_t)__bfloat16_as_ushort(h0) | ((uint32_t)__bfloat16_as_ushort(h1) << 16);
                    *reinterpret_cast<uint32_t*>(o1 + off) =
                        (uint32_t)__bfloat16_as_ushort(l0) | ((uint32_t)__bfloat16_as_ushort(l1) << 16);
                }
                if (r1 < Mvalid) {
                    long off = (long)bz * sO + (long)r1 * ldo + col;
                    __nv_bfloat16 h0, l0, h1, l1;
                    split2(v10, h0, l0); split2(v11, h1, l1);
                    *reinterpret_cast<uint32_t*>(o0 + off) =
                        (uint32_t)__bfloat16_as_ushort(h0) | ((uint32_t)__bfloat16_as_ushort(h1) << 16);
                    *reinterpret_cast<uint32_t*>(o1 + off) =
                        (uint32_t)__bfloat16_as_ushort(l0) | ((uint32_t)__bfloat16_as_ushort(l1) << 16);
                }
            } else {
                if (r0 < Mvalid)
                    *reinterpret_cast<float2*>(of + (long)bz * sO + (long)r0 * ldo + col) =
                        make_float2(v00, v01);
                if (r1 < Mvalid)
                    *reinterpret_cast<float2*>(of + (long)bz * sO + (long)r1 * ldo + col) =
                        make_float2(v10, v11);
            }
        }
    }
}

// ============ conversions ============
__global__ void convw_kernel(const float* __restrict__ s, __nv_bfloat16* __restrict__ dh,
                             __nv_bfloat16* __restrict__ dl, int count)
{
    for (int i = blockIdx.x * blockDim.x + threadIdx.x; i < count; i += gridDim.x * blockDim.x) {
        __nv_bfloat16 h, l; split2(s[i], h, l);
        dh[i] = h; dl[i] = l;
    }
}
__global__ void convx_kernel(const float* __restrict__ x)
{
    long i = (long)blockIdx.x * blockDim.x + threadIdx.x;
    const long total = (long)NB * NC * NN;
    for (; i < total; i += (long)gridDim.x * blockDim.x) {
        __nv_bfloat16 h, l; split2(x[i], h, l);
        g_xh[i] = h; g_xl[i] = l;
    }
}

// ============ token MLP ============
__global__ void tk1_kernel(const float* __restrict__ t, const float* __restrict__ W,
                           const float* __restrict__ bias)
{
    int gw = (blockIdx.x * blockDim.x + threadIdx.x) >> 5;
    int lane = threadIdx.x & 31;
    int o = gw % NHID, b = gw / NHID;
    const float* tr = t + (long)b * NC;
    const float* wr = W + (long)o * NC;
    float s = 0.f;
    for (int k = lane; k < NC; k += 32) s = fmaf(tr[k], wr[k], s);
#pragma unroll
    for (int off = 16; off > 0; off >>= 1) s += __shfl_xor_sync(0xffffffffu, s, off);
    if (lane == 0) g_tht[b * NHID + o] = fmaxf(s + bias[o], 0.f);
}
__global__ void tk2_kernel(const float* __restrict__ W, const float* __restrict__ bias)
{
    int gw = (blockIdx.x * blockDim.x + threadIdx.x) >> 5;
    int lane = threadIdx.x & 31;
    int o = gw % NG, b = gw / NG;
    const float* hr = g_tht + (long)b * NHID;
    const float* wr = W + (long)o * NHID;
    float s = 0.f;
    for (int k = lane; k < NHID; k += 32) s = fmaf(hr[k], wr[k], s);
#pragma unroll
    for (int off = 16; off > 0; off >>= 1) s += __shfl_xor_sync(0xffffffffu, s, off);
    if (lane == 0) g_tk[b * NG + o] = s + bias[o];
}

// ============ column norms of f ============
__global__ void colnorm_kernel()
{
    int idx = blockIdx.x * blockDim.x + threadIdx.x;
    if (idx >= NB * NN) return;
    int b = idx >> 10, j = idx & (NN - 1);
    long base = (long)b * NL * NN + j;
    float s = 0.f;
    for (int l = 0; l < NL; l++) {
        float v = __bfloat162float(g_fh[base + (long)l * NN]) +
                  __bfloat162float(g_fl[base + (long)l * NN]);
        s = fmaf(v, v, s);
    }
    g_norms[idx] = fmaxf(sqrtf(s), 1e-12f);
}

// ============ fn: [l][n] and transposed [n][l] ============
__global__ void fnt_kernel()
{
    __shared__ float tile[32][33];
    int b = blockIdx.z, l0 = blockIdx.y * 32, n0 = blockIdx.x * 32;
    int tx = threadIdx.x, ty = threadIdx.y;
    long fb = (long)b * NL * NN;
#pragma unroll
    for (int i = 0; i < 4; i++) {
        int l = l0 + ty + i * 8;
        long off = fb + (long)l * NN + n0 + tx;
        tile[ty + i * 8][tx] = __bfloat162float(g_fh[off]) + __bfloat162float(g_fl[off]);
    }
    __syncthreads();
    float nv = g_norms[b * NN + n0 + tx];
#pragma unroll
    for (int i = 0; i < 4; i++) {
        int l = l0 + ty + i * 8;
        g_fnk[fb + (long)l * NN + n0 + tx] = __float2bfloat16(tile[ty + i * 8][tx] / nv);
    }
#pragma unroll
    for (int i = 0; i < 4; i++) {
        int r = ty + i * 8;
        float nv2 = g_norms[b * NN + n0 + r];
        g_fnj[((long)b * NN + n0 + r) * NL + l0 + tx] =
            __float2bfloat16(tile[tx][r] / nv2);
    }
}

// ============ Sinkhorn (parallel u/v kernels) ============
__global__ void sk_u_kernel(const float* __restrict__ pdust)
{
    const float NORMC = -logf((float)(NM + NN));
    const float LOGN = logf((float)NN);
    int gw = (blockIdx.x * blockDim.x + threadIdx.x) >> 5;
    int lane = threadIdx.x & 31;
    if (gw >= NB * (NM + 1)) return;
    int i = gw % (NM + 1), b = gw / (NM + 1);

    const float4* v4 = reinterpret_cast<const float4*>(g_v + b * NN);
    float xs[32];
    if (i < NM) {
        const float4* p4 = reinterpret_cast<const float4*>(g_p + ((long)b * NM + i) * NN);
#pragma unroll
        for (int w = 0; w < 8; w++) {
            float4 pv = p4[w * 32 + lane];
            float4 vv = v4[w * 32 + lane];
            xs[4*w]   = pv.x + vv.x; xs[4*w+1] = pv.y + vv.y;
            xs[4*w+2] = pv.z + vv.z; xs[4*w+3] = pv.w + vv.w;
        }
    } else {
        float dust = *pdust;
#pragma unroll
        for (int w = 0; w < 8; w++) {
            float4 vv = v4[w * 32 + lane];
            xs[4*w]   = dust + vv.x; xs[4*w+1] = dust + vv.y;
            xs[4*w+2] = dust + vv.z; xs[4*w+3] = dust + vv.w;
        }
    }
    float mx = xs[0];
#pragma unroll
    for (int q = 1; q < 32; q++) mx = fmaxf(mx, xs[q]);
#pragma unroll
    for (int off = 16; off > 0; off >>= 1) mx = fmaxf(mx, __shfl_xor_sync(0xffffffffu, mx, off));
    float s = 0.f;
#pragma unroll
    for (int q = 0; q < 32; q++) s += __expf(xs[q] - mx);
#pragma unroll
    for (int off = 16; off > 0; off >>= 1) s += __shfl_xor_sync(0xffffffffu, s, off);
    if (lane == 0)
        g_u[b * (NM + 1) + i] = ((i < NM) ? NORMC : (LOGN + NORMC)) - (mx + __logf(s));
}

__global__ void sk_v_kernel(const float* __restrict__ pdust)
{
    const float NORMC = -logf((float)(NM + NN));
    __shared__ float su[NM + 1];
    int b = blockIdx.x >> 2, q = blockIdx.x & 3;
    int tid = threadIdx.x;
    if (tid <= NM) su[tid] = g_u[b * (NM + 1) + tid];
    __syncthreads();
    int j = q * 256 + tid;
    const float* pb = g_p + (long)b * NM * NN + j;
    float mx = *pdust + su[NM];
    float s = 1.f;
#pragma unroll 8
    for (int i = 0; i < NM; i++) {
        float x = pb[(long)i * NN] + su[i];
        if (x > mx) { s = s * __expf(mx - x) + 1.f; mx = x; }
        else        { s += __expf(x - mx); }
    }
    g_v[b * NN + j] = NORMC - (mx + __logf(s));
}

__global__ void cterm_kernel(const float* __restrict__ pbp)
{
    const float NORMC = -logf((float)(NM + NN));
    int idx = blockIdx.x * blockDim.x + threadIdx.x;
    if (idx >= NB * NN) return;
    g_v[idx] = g_v[idx] - NORMC - (*pbp) * __logf(g_bw[idx]);
}

__global__ void pfinal_kernel()
{
    long idx = (long)blockIdx.x * blockDim.x + threadIdx.x;
    int b = (int)(idx >> 16);
    int i = (int)((idx >> 10) & 63);
    int j = (int)(idx & 1023);
    float val = __expf(g_p[idx] + g_u[b * (NM + 1) + i] + g_v[b * NN + j]);
    __nv_bfloat16 h, l; split2(val, h, l);
    long o = ((long)b * NN + j) * NM + i;
    g_Pth[o] = h; g_Ptl[o] = l;
}

// ============ final normalize + concat ============
__global__ void final_kernel(float* __restrict__ out)
{
    const int b = blockIdx.x, tid = threadIdx.x;
    __shared__ float sred[256];
    __shared__ float cnorm[NM];
    __shared__ float stk, stot;

    float v = g_tk[b * NG + tid];
    sred[tid] = v * v;
    __syncthreads();
    for (int s = 128; s > 0; s >>= 1) { if (tid < s) sred[tid] += sred[tid + s]; __syncthreads(); }
    if (tid == 0) stk = fmaxf(sqrtf(sred[0]), 1e-12f);
    __syncthreads();
    {
        int m = tid & 63, part = tid >> 6;
        const float* ab = g_agg + (long)b * NL * NM;
        float s = 0.f;
        for (int l = part * 32; l < part * 32 + 32; l++) {
            float x = ab[(long)l * NM + m];
            s = fmaf(x, x, s);
        }
        sred[tid] = s;
        __syncthreads();
        if (tid < 64)
            cnorm[tid] = fmaxf(sqrtf(sred[tid] + sred[tid+64] + sred[tid+128] + sred[tid+192]), 1e-12f);
        __syncthreads();
    }
    const int ROW = NG + NL * NM;
    float* orow = out + (long)b * ROW;
    float tot = 0.f;
    for (int idx = tid; idx < ROW; idx += 256) {
        float val;
        if (idx < NG) val = g_tk[b * NG + idx] / stk;
        else {
            int r = idx - NG;
            val = g_agg[((long)b * NL + (r >> 6)) * NM + (r & 63)] / cnorm[r & 63];
        }
        orow[idx] = val;
        tot += val * val;
    }
    sred[tid] = tot;
    __syncthreads();
    for (int s = 128; s > 0; s >>= 1) { if (tid < s) sred[tid] += sred[tid + s]; __syncthreads(); }
    if (tid == 0) stot = fmaxf(sqrtf(sred[0]), 1e-12f);
    __syncthreads();
    for (int idx = tid; idx < ROW; idx += 256) orow[idx] /= stot;
}

// ============ launcher ============
extern "C" void kernel_launch(void* const* d_in, const int* in_sizes, int n_in,
                              void* d_out, int out_size)
{
    (void)in_sizes; (void)n_in; (void)out_size;
    const float* x    = (const float*)d_in[0];
    const float* t    = (const float*)d_in[1];
    const float* Wc1  = (const float*)d_in[2];
    const float* bc1  = (const float*)d_in[3];
    const float* Wc2  = (const float*)d_in[4];
    const float* bc2  = (const float*)d_in[5];
    const float* Ws1  = (const float*)d_in[6];
    const float* bs1  = (const float*)d_in[7];
    const float* Ws2  = (const float*)d_in[8];
    const float* bs2  = (const float*)d_in[9];
    const float* Wt1  = (const float*)d_in[10];
    const float* bt1  = (const float*)d_in[11];
    const float* Wt2  = (const float*)d_in[12];
    const float* bt2  = (const float*)d_in[13];
    const float* dust = (const float*)d_in[14];
    const float* ba   = (const float*)d_in[15];
    const float* bbp  = (const float*)d_in[16];
    const float* bp   = (const float*)d_in[17];
    float* out = (float*)d_out;

    __nv_bfloat16 *xh, *xl, *hh, *hl, *fh, *fl, *fnj, *fnk, *Pth, *Ptl;
    __nv_bfloat16 *w1h, *w1l, *w2h, *w2l, *wch, *wcl, *wsh, *wsl;
    float *pp, *pbw, *pagg, *pv;
    cudaGetSymbolAddress((void**)&xh, g_xh);   cudaGetSymbolAddress((void**)&xl, g_xl);
    cudaGetSymbolAddress((void**)&hh, g_hh);   cudaGetSymbolAddress((void**)&hl, g_hl);
    cudaGetSymbolAddress((void**)&fh, g_fh);   cudaGetSymbolAddress((void**)&fl, g_fl);
    cudaGetSymbolAddress((void**)&fnj, g_fnj); cudaGetSymbolAddress((void**)&fnk, g_fnk);
    cudaGetSymbolAddress((void**)&Pth, g_Pth); cudaGetSymbolAddress((void**)&Ptl, g_Ptl);
    cudaGetSymbolAddress((void**)&w1h, g_w1h); cudaGetSymbolAddress((void**)&w1l, g_w1l);
    cudaGetSymbolAddress((void**)&w2h, g_w2h); cudaGetSymbolAddress((void**)&w2l, g_w2l);
    cudaGetSymbolAddress((void**)&wch, g_wch); cudaGetSymbolAddress((void**)&wcl, g_wcl);
    cudaGetSymbolAddress((void**)&wsh, g_wsh); cudaGetSymbolAddress((void**)&wsl, g_wsl);
    cudaGetSymbolAddress((void**)&pp, g_p);    cudaGetSymbolAddress((void**)&pbw, g_bw);
    cudaGetSymbolAddress((void**)&pagg, g_agg);
    cudaGetSymbolAddress((void**)&pv, g_v);

    cudaFuncSetAttribute(mma_gemm_kernel, cudaFuncAttributeMaxDynamicSharedMemorySize, SMEM_TOTAL);

    // splits
    convw_kernel<<<256, 256>>>(Wc1, w1h, w1l, NHID * NC);
    convw_kernel<<<256, 256>>>(Ws1, w2h, w2l, NHID * NC);
    convw_kernel<<<64, 256>>>(Wc2, wch, wcl, NL * NHID);
    convw_kernel<<<32, 256>>>(Ws2, wsh, wsl, NM * NHID);
    convx_kernel<<<8192, 256>>>(x);

    // token MLP
    tk1_kernel<<<(NB * NHID * 32) / 256, 256>>>(t, Wt1, bt1);
    tk2_kernel<<<(NB * NG * 32) / 256, 256>>>(Wt2, bt2);

    // conv stacks
    mma_gemm_kernel<<<dim3(NN/128, NHID/128, NB), 256, SMEM_TOTAL>>>(
        w1h, w1l, 0, xh, xl, (long)NC * NN,
        NC, NN, NHID, NN, bc1, 1, 0, hh, hl, nullptr, (long)NHID * NN, NN, nullptr, nullptr);
    mma_gemm_kernel<<<dim3(NN/128, 1, NB), 256, SMEM_TOTAL>>>(
        wch, wcl, 0, hh, hl, (long)NHID * NN,
        NHID, NN, NL, NN, bc2, 0, 0, fh, fl, nullptr, (long)NL * NN, NN, nullptr, nullptr);
    mma_gemm_kernel<<<dim3(NN/128, NHID/128, NB), 256, SMEM_TOTAL>>>(
        w2h, w2l, 0, xh, xl, (long)NC * NN,
        NC, NN, NHID, NN, bs1, 1, 0, hh, hl, nullptr, (long)NHID * NN, NN, nullptr, nullptr);
    mma_gemm_kernel<<<dim3(NN/128, 1, NB), 256, SMEM_TOTAL>>>(
        wsh, wsl, 0, hh, hl, (long)NHID * NN,
        NHID, NN, NM, NN, bs2, 0, 1, nullptr, nullptr, pp, (long)NM * NN, NN, nullptr, nullptr);

    // burst reweighting
    colnorm_kernel<<<(NB * NN) / 256, 256>>>();
    fnt_kernel<<<dim3(NN/32, NL/32, NB), dim3(32, 8)>>>();
    cudaMemsetAsync(pbw, 0, (size_t)NB * NN * sizeof(float));
    mma_gemm_kernel<<<dim3(NN/128, NN/128, NB), 256, SMEM_TOTAL>>>(
        fnj, nullptr, (long)NN * NL, fnk, nullptr, (long)NL * NN,
        NL, NN, NN, NN, nullptr, 0, 2, nullptr, nullptr, nullptr, 0, 0, ba, bbp);

    // Sinkhorn
    cudaMemsetAsync(pv, 0, (size_t)NB * NN * sizeof(float));
    for (int it = 0; it < 3; it++) {
        sk_u_kernel<<<(NB * (NM + 1) * 32 + 255) / 256, 256>>>(dust);
        sk_v_kernel<<<NB * 4, 256>>>(dust);
    }
    cterm_kernel<<<(NB * NN) / 256, 256>>>(bp);
    pfinal_kernel<<<(NB * NM * NN) / 256, 256>>>();

    // agg
    mma_gemm_kernel<<<dim3(1, 1, NB), 256, SMEM_TOTAL>>>(
        fh, fl, (long)NL * NN, Pth, Ptl, (long)NN * NM,
        NN, NM, NL, NM, nullptr, 0, 1, nullptr, nullptr, pagg, (long)NL * NM, NM, nullptr, nullptr);

    final_kernel<<<NB, 256>>>(out);
}

// round 7
// speedup vs baseline: 1.6700x; 1.3206x over previous
#include <cuda_runtime.h>
#include <cuda_fp16.h>
#include <math.h>
#include <stdint.h>

#define NB 32
#define NC 1536
#define NN 1024
#define NHID 512
#define NL 128
#define NM 64
#define NG 256

// ---- smem tile geometry (fp16) ----
#define APAD 40
#define BPAD 136
#define A_BYTES (128 * APAD * 2)            // 10240
#define B_BYTES (32 * BPAD * 2)             // 8704
#define STAGE_BYTES (2 * A_BYTES + B_BYTES) // 29184 (A hi + A lo + B single)
#define SMEM_TOTAL (2 * STAGE_BYTES)        // 58368

// ---- scratch ----
__device__ __half g_x  [(size_t)NB * NC * NN];          // x fp16 (single)
__device__ __half g_h  [(size_t)NB * 1024 * NN];        // fused h (rows 0-511 c, 512-1023 s)
__device__ __half g_f  [(size_t)NB * NL * NN];
__device__ __half g_fnj[(size_t)NB * NN * NL];
__device__ __half g_fnk[(size_t)NB * NL * NN];
__device__ float  g_p  [(size_t)NB * NM * NN];
__device__ __half g_Pt [(size_t)NB * NN * NM];          // P^T [n][m] fp16
__device__ __half g_wAh[1024 * NC], g_wAl[1024 * NC];   // fused [Wc1;Ws1] split
__device__ float  g_bA [1024];
__device__ __half g_wch[NL * NHID], g_wcl[NL * NHID];
__device__ __half g_wsh[NM * NHID], g_wsl[NM * NHID];
__device__ float g_u[NB * (NM + 1)];
__device__ float g_v[NB * NN];
__device__ float g_norms[NB * NN];
__device__ float g_bw[NB * NN];
__device__ float g_agg[NB * NL * NM];
__device__ float g_tht[NB * NHID];
__device__ float g_tk[NB * NG];

__device__ __forceinline__ void split2h(float v, __half& h, __half& l) {
    h = __float2half_rn(v);
    l = __float2half_rn(v - __half2float(h));
}
__device__ __forceinline__ uint32_t smem_u32(const void* p) {
    uint32_t a;
    asm("{ .reg .u64 t; cvta.to.shared.u64 t, %1; cvt.u32.u64 %0, t; }" : "=r"(a) : "l"(p));
    return a;
}
__device__ __forceinline__ void cp16(uint32_t d, const void* s, bool pred) {
    int sz = pred ? 16 : 0;
    asm volatile("cp.async.cg.shared.global [%0], [%1], 16, %2;"
                 :: "r"(d), "l"(s), "r"(sz) : "memory");
}
#define CP_COMMIT() asm volatile("cp.async.commit_group;" ::: "memory")
#define CP_WAIT0()  asm volatile("cp.async.wait_group 0;" ::: "memory")

__device__ __forceinline__ void ldmx4(uint32_t* r, uint32_t a) {
    asm volatile("ldmatrix.sync.aligned.m8n8.x4.shared.b16 {%0,%1,%2,%3}, [%4];"
        : "=r"(r[0]), "=r"(r[1]), "=r"(r[2]), "=r"(r[3]) : "r"(a));
}
__device__ __forceinline__ void ldmx2t(uint32_t* r, uint32_t a) {
    asm volatile("ldmatrix.sync.aligned.m8n8.x2.trans.shared.b16 {%0,%1}, [%2];"
        : "=r"(r[0]), "=r"(r[1]) : "r"(a));
}
__device__ __forceinline__ void mma16816(float* d, const uint32_t* a, const uint32_t* b) {
    asm volatile("mma.sync.aligned.m16n8k16.row.col.f32.f16.f16.f32 "
        "{%0,%1,%2,%3}, {%4,%5,%6,%7}, {%8,%9}, {%0,%1,%2,%3};"
        : "+f"(d[0]), "+f"(d[1]), "+f"(d[2]), "+f"(d[3])
        : "r"(a[0]), "r"(a[1]), "r"(a[2]), "r"(a[3]), "r"(b[0]), "r"(b[1]));
}

// ================= MMA GEMM: D[m][n]=sum_k A[m][k]B[k][n], A split fp16 (2 passes) =================
// mode 0: fp16 out (+bias[m], opt relu); 1: fp32 out (+bias if given); 2: burst sigmoid-reduce.
__global__ void __launch_bounds__(256, 2) mma_gemm_kernel(
    const __half* __restrict__ Ah, const __half* __restrict__ Al, long sA,
    const __half* __restrict__ B, long sB,
    int K, int ldB, int Mvalid, int Nvalid,
    const float* __restrict__ bias, int relu, int mode,
    __half* __restrict__ oh, float* __restrict__ of, long sO, int ldo,
    const float* __restrict__ pa, const float* __restrict__ pb)
{
    extern __shared__ char smem[];
    const uint32_t su = smem_u32(smem);
    const int tid = threadIdx.x, lane = tid & 31, wid = tid >> 5;
    const int wm = wid >> 2, wn = wid & 3;
    const int bz = blockIdx.z, n0 = blockIdx.x * 128, m0 = blockIdx.y * 128;
    const bool x2 = (Al != nullptr);

    const __half* A_h = Ah + (long)bz * sA + (long)m0 * K;
    const __half* A_l = x2 ? Al + (long)bz * sA + (long)m0 * K : A_h;
    const __half* B_p = B + (long)bz * sB;
    const int mMax = (Mvalid - m0 < 128) ? (Mvalid - m0) : 128;

    float acc[4][4][4];
#pragma unroll
    for (int i = 0; i < 4; i++)
#pragma unroll
        for (int j = 0; j < 4; j++)
#pragma unroll
            for (int q = 0; q < 4; q++) acc[i][j][q] = 0.f;

    const int nc = K >> 5;

    auto prefetch = [&](int c, int st) {
        uint32_t sa = su + st * STAGE_BYTES;
        long kb = (long)c * 32;
#pragma unroll
        for (int i = 0; i < 2; i++) {
            int idx = tid + i * 256;
            int row = idx >> 2, cc = idx & 3;
            uint32_t doff = sa + row * (APAD * 2) + cc * 16;
            bool p = row < mMax;
            cp16(doff, A_h + (long)row * K + kb + cc * 8, p);
            if (x2) cp16(doff + A_BYTES, A_l + (long)row * K + kb + cc * 8, p);
        }
#pragma unroll
        for (int i = 0; i < 2; i++) {
            int idx = tid + i * 256;
            int row = idx >> 4, cc = idx & 15;
            uint32_t doff = sa + 2 * A_BYTES + row * (BPAD * 2) + cc * 16;
            bool p = (n0 + cc * 8) < Nvalid;
            cp16(doff, B_p + (kb + row) * (long)ldB + n0 + cc * 8, p);
        }
    };

    prefetch(0, 0);
    CP_COMMIT();

    for (int c = 0; c < nc; c++) {
        CP_WAIT0();
        __syncthreads();
        if (c + 1 < nc) { prefetch(c + 1, (c + 1) & 1); CP_COMMIT(); }

        uint32_t sa = su + (c & 1) * STAGE_BYTES;
#pragma unroll
        for (int kk = 0; kk < 2; kk++) {
            uint32_t afh[4][4], afl[4][4];
#pragma unroll
            for (int mi = 0; mi < 4; mi++) {
                uint32_t ad = sa + ((wm * 64 + mi * 16 + (lane & 15)) * APAD
                                    + kk * 16 + (lane >> 4) * 8) * 2;
                ldmx4(afh[mi], ad);
                if (x2) ldmx4(afl[mi], ad + A_BYTES);
            }
            uint32_t bf[4][2];
#pragma unroll
            for (int ni = 0; ni < 4; ni++) {
                uint32_t bd = sa + 2 * A_BYTES
                            + (kk * 16 + (lane & 15)) * (BPAD * 2)
                            + (wn * 32 + ni * 8) * 2;
                ldmx2t(bf[ni], bd);
            }
            // pass 1: hi-A x B (16 independent MMAs)
#pragma unroll
            for (int ni = 0; ni < 4; ni++)
#pragma unroll
                for (int mi = 0; mi < 4; mi++)
                    mma16816(acc[mi][ni], afh[mi], bf[ni]);
            // pass 2: lo-A x B
            if (x2) {
#pragma unroll
                for (int ni = 0; ni < 4; ni++)
#pragma unroll
                    for (int mi = 0; mi < 4; mi++)
                        mma16816(acc[mi][ni], afl[mi], bf[ni]);
            }
        }
    }

    const int g = lane >> 2, tq = lane & 3;
    if (mode == 2) {
        const float a = *pa, bb = *pb;
        const bool fast = (fabsf(a) + fabsf(bb)) <= 1.0f;
#pragma unroll
        for (int mi = 0; mi < 4; mi++) {
            float r0 = 0.f, r1 = 0.f;
#pragma unroll
            for (int ni = 0; ni < 4; ni++) {
#pragma unroll
                for (int q = 0; q < 4; q++) {
                    float z = a * acc[mi][ni][q] + bb;
                    float s;
                    if (fast) {
                        float tt = 0.5f * z, t2 = tt * tt;
                        float th = tt * (1.f + t2 * (-0.3333333333f
                                   + t2 * (0.1333333333f - t2 * 0.05396825397f)));
                        s = 0.5f + 0.5f * th;
                    } else {
                        s = 1.f / (1.f + __expf(-z));
                    }
                    if (q < 2) r0 += s; else r1 += s;
                }
            }
            r0 += __shfl_xor_sync(0xffffffffu, r0, 1);
            r0 += __shfl_xor_sync(0xffffffffu, r0, 2);
            r1 += __shfl_xor_sync(0xffffffffu, r1, 1);
            r1 += __shfl_xor_sync(0xffffffffu, r1, 2);
            if (tq == 0) {
                int j = m0 + wm * 64 + mi * 16 + g;
                atomicAdd(&g_bw[bz * NN + j], r0);
                atomicAdd(&g_bw[bz * NN + j + 8], r1);
            }
        }
        return;
    }

#pragma unroll
    for (int mi = 0; mi < 4; mi++) {
        int r0 = m0 + wm * 64 + mi * 16 + g;
        int r1 = r0 + 8;
        float b0v = (bias && r0 < Mvalid) ? bias[r0] : 0.f;
        float b1v = (bias && r1 < Mvalid) ? bias[r1] : 0.f;
#pragma unroll
        for (int ni = 0; ni < 4; ni++) {
            int col = n0 + wn * 32 + ni * 8 + tq * 2;
            if (col >= Nvalid) continue;
            float v00 = acc[mi][ni][0] + b0v, v01 = acc[mi][ni][1] + b0v;
            float v10 = acc[mi][ni][2] + b1v, v11 = acc[mi][ni][3] + b1v;
            if (relu) {
                v00 = fmaxf(v00, 0.f); v01 = fmaxf(v01, 0.f);
                v10 = fmaxf(v10, 0.f); v11 = fmaxf(v11, 0.f);
            }
            if (mode == 0) {
                if (r0 < Mvalid) {
                    long off = (long)bz * sO + (long)r0 * ldo + col;
                    __half h0 = __float2half_rn(v00), h1 = __float2half_rn(v01);
                    *reinterpret_cast<uint32_t*>(oh + off) =
                        (uint32_t)__half_as_ushort(h0) | ((uint32_t)__half_as_ushort(h1) << 16);
                }
                if (r1 < Mvalid) {
                    long off = (long)bz * sO + (long)r1 * ldo + col;
                    __half h0 = __float2half_rn(v10), h1 = __float2half_rn(v11);
                    *reinterpret_cast<uint32_t*>(oh + off) =
                        (uint32_t)__half_as_ushort(h0) | ((uint32_t)__half_as_ushort(h1) << 16);
                }
            } else {
                if (r0 < Mvalid)
                    *reinterpret_cast<float2*>(of + (long)bz * sO + (long)r0 * ldo + col) =
                        make_float2(v00, v01);
                if (r1 < Mvalid)
                    *reinterpret_cast<float2*>(of + (long)bz * sO + (long)r1 * ldo + col) =
                        make_float2(v10, v11);
            }
        }
    }
}

// ============ conversions ============
__global__ void convw_kernel(const float* __restrict__ s, __half* __restrict__ dh,
                             __half* __restrict__ dl, int count)
{
    for (int i = blockIdx.x * blockDim.x + threadIdx.x; i < count; i += gridDim.x * blockDim.x) {
        __half h, l; split2h(s[i], h, l);
        dh[i] = h; dl[i] = l;
    }
}
__global__ void convx_kernel(const float* __restrict__ x)
{
    long i = (long)blockIdx.x * blockDim.x + threadIdx.x;
    const long total = (long)NB * NC * NN / 4;
    for (; i < total; i += (long)gridDim.x * blockDim.x) {
        float4 v = reinterpret_cast<const float4*>(x)[i];
        __half2 a = __floats2half2_rn(v.x, v.y);
        __half2 b = __floats2half2_rn(v.z, v.w);
        reinterpret_cast<uint2*>(g_x)[i] =
            make_uint2(*reinterpret_cast<uint32_t*>(&a), *reinterpret_cast<uint32_t*>(&b));
    }
}

// ============ token MLP ============
__global__ void tk1_kernel(const float* __restrict__ t, const float* __restrict__ W,
                           const float* __restrict__ bias)
{
    int gw = (blockIdx.x * blockDim.x + threadIdx.x) >> 5;
    int lane = threadIdx.x & 31;
    int o = gw % NHID, b = gw / NHID;
    const float* tr = t + (long)b * NC;
    const float* wr = W + (long)o * NC;
    float s = 0.f;
    for (int k = lane; k < NC; k += 32) s = fmaf(tr[k], wr[k], s);
#pragma unroll
    for (int off = 16; off > 0; off >>= 1) s += __shfl_xor_sync(0xffffffffu, s, off);
    if (lane == 0) g_tht[b * NHID + o] = fmaxf(s + bias[o], 0.f);
}
__global__ void tk2_kernel(const float* __restrict__ W, const float* __restrict__ bias)
{
    int gw = (blockIdx.x * blockDim.x + threadIdx.x) >> 5;
    int lane = threadIdx.x & 31;
    int o = gw % NG, b = gw / NG;
    const float* hr = g_tht + (long)b * NHID;
    const float* wr = W + (long)o * NHID;
    float s = 0.f;
    for (int k = lane; k < NHID; k += 32) s = fmaf(hr[k], wr[k], s);
#pragma unroll
    for (int off = 16; off > 0; off >>= 1) s += __shfl_xor_sync(0xffffffffu, s, off);
    if (lane == 0) g_tk[b * NG + o] = s + bias[o];
}

// ============ column norms of f ============
__global__ void colnorm_kernel()
{
    int idx = blockIdx.x * blockDim.x + threadIdx.x;
    if (idx >= NB * NN) return;
    int b = idx >> 10, j = idx & (NN - 1);
    long base = (long)b * NL * NN + j;
    float s = 0.f;
    for (int l = 0; l < NL; l++) {
        float v = __half2float(g_f[base + (long)l * NN]);
        s = fmaf(v, v, s);
    }
    g_norms[idx] = fmaxf(sqrtf(s), 1e-12f);
}

// ============ fn: [l][n] and transposed [n][l] ============
__global__ void fnt_kernel()
{
    __shared__ float tile[32][33];
    int b = blockIdx.z, l0 = blockIdx.y * 32, n0 = blockIdx.x * 32;
    int tx = threadIdx.x, ty = threadIdx.y;
    long fb = (long)b * NL * NN;
#pragma unroll
    for (int i = 0; i < 4; i++) {
        int l = l0 + ty + i * 8;
        tile[ty + i * 8][tx] = __half2float(g_f[fb + (long)l * NN + n0 + tx]);
    }
    __syncthreads();
    float nv = g_norms[b * NN + n0 + tx];
#pragma unroll
    for (int i = 0; i < 4; i++) {
        int l = l0 + ty + i * 8;
        g_fnk[fb + (long)l * NN + n0 + tx] = __float2half_rn(tile[ty + i * 8][tx] / nv);
    }
#pragma unroll
    for (int i = 0; i < 4; i++) {
        int r = ty + i * 8;
        float nv2 = g_norms[b * NN + n0 + r];
        g_fnj[((long)b * NN + n0 + r) * NL + l0 + tx] =
            __float2half_rn(tile[tx][r] / nv2);
    }
}

// ============ Sinkhorn (parallel u/v kernels) ============
__global__ void sk_u_kernel(const float* __restrict__ pdust)
{
    const float NORMC = -logf((float)(NM + NN));
    const float LOGN = logf((float)NN);
    int gw = (blockIdx.x * blockDim.x + threadIdx.x) >> 5;
    int lane = threadIdx.x & 31;
    if (gw >= NB * (NM + 1)) return;
    int i = gw % (NM + 1), b = gw / (NM + 1);

    const float4* v4 = reinterpret_cast<const float4*>(g_v + b * NN);
    float xs[32];
    if (i < NM) {
        const float4* p4 = reinterpret_cast<const float4*>(g_p + ((long)b * NM + i) * NN);
#pragma unroll
        for (int w = 0; w < 8; w++) {
            float4 pv = p4[w * 32 + lane];
            float4 vv = v4[w * 32 + lane];
            xs[4*w]   = pv.x + vv.x; xs[4*w+1] = pv.y + vv.y;
            xs[4*w+2] = pv.z + vv.z; xs[4*w+3] = pv.w + vv.w;
        }
    } else {
        float dust = *pdust;
#pragma unroll
        for (int w = 0; w < 8; w++) {
            float4 vv = v4[w * 32 + lane];
            xs[4*w]   = dust + vv.x; xs[4*w+1] = dust + vv.y;
            xs[4*w+2] = dust + vv.z; xs[4*w+3] = dust + vv.w;
        }
    }
    float mx = xs[0];
#pragma unroll
    for (int q = 1; q < 32; q++) mx = fmaxf(mx, xs[q]);
#pragma unroll
    for (int off = 16; off > 0; off >>= 1) mx = fmaxf(mx, __shfl_xor_sync(0xffffffffu, mx, off));
    float s = 0.f;
#pragma unroll
    for (int q = 0; q < 32; q++) s += __expf(xs[q] - mx);
#pragma unroll
    for (int off = 16; off > 0; off >>= 1) s += __shfl_xor_sync(0xffffffffu, s, off);
    if (lane == 0)
        g_u[b * (NM + 1) + i] = ((i < NM) ? NORMC : (LOGN + NORMC)) - (mx + __logf(s));
}

__global__ void sk_v_kernel(const float* __restrict__ pdust)
{
    const float NORMC = -logf((float)(NM + NN));
    __shared__ float su[NM + 1];
    int b = blockIdx.x >> 2, q = blockIdx.x & 3;
    int tid = threadIdx.x;
    if (tid <= NM) su[tid] = g_u[b * (NM + 1) + tid];
    __syncthreads();
    int j = q * 256 + tid;
    const float* pb = g_p + (long)b * NM * NN + j;
    float mx = *pdust + su[NM];
    float s = 1.f;
#pragma unroll 8
    for (int i = 0; i < NM; i++) {
        float x = pb[(long)i * NN] + su[i];
        if (x > mx) { s = s * __expf(mx - x) + 1.f; mx = x; }
        else        { s += __expf(x - mx); }
    }
    g_v[b * NN + j] = NORMC - (mx + __logf(s));
}

__global__ void cterm_kernel(const float* __restrict__ pbp)
{
    const float NORMC = -logf((float)(NM + NN));
    int idx = blockIdx.x * blockDim.x + threadIdx.x;
    if (idx >= NB * NN) return;
    g_v[idx] = g_v[idx] - NORMC - (*pbp) * __logf(g_bw[idx]);
}

__global__ void pfinal_kernel()
{
    long idx = (long)blockIdx.x * blockDim.x + threadIdx.x;
    int b = (int)(idx >> 16);
    int i = (int)((idx >> 10) & 63);
    int j = (int)(idx & 1023);
    float val = __expf(g_p[idx] + g_u[b * (NM + 1) + i] + g_v[b * NN + j]);
    g_Pt[((long)b * NN + j) * NM + i] = __float2half_rn(val);
}

// ============ final normalize + concat ============
__global__ void final_kernel(float* __restrict__ out)
{
    const int b = blockIdx.x, tid = threadIdx.x;
    __shared__ float sred[256];
    __shared__ float cnorm[NM];
    __shared__ float stk, stot;

    float v = g_tk[b * NG + tid];
    sred[tid] = v * v;
    __syncthreads();
    for (int s = 128; s > 0; s >>= 1) { if (tid < s) sred[tid] += sred[tid + s]; __syncthreads(); }
    if (tid == 0) stk = fmaxf(sqrtf(sred[0]), 1e-12f);
    __syncthreads();
    {
        int m = tid & 63, part = tid >> 6;
        const float* ab = g_agg + (long)b * NL * NM;
        float s = 0.f;
        for (int l = part * 32; l < part * 32 + 32; l++) {
            float x = ab[(long)l * NM + m];
            s = fmaf(x, x, s);
        }
        sred[tid] = s;
        __syncthreads();
        if (tid < 64)
            cnorm[tid] = fmaxf(sqrtf(sred[tid] + sred[tid+64] + sred[tid+128] + sred[tid+192]), 1e-12f);
        __syncthreads();
    }
    const int ROW = NG + NL * NM;
    float* orow = out + (long)b * ROW;
    float tot = 0.f;
    for (int idx = tid; idx < ROW; idx += 256) {
        float val;
        if (idx < NG) val = g_tk[b * NG + idx] / stk;
        else {
            int r = idx - NG;
            val = g_agg[((long)b * NL + (r >> 6)) * NM + (r & 63)] / cnorm[r & 63];
        }
        orow[idx] = val;
        tot += val * val;
    }
    sred[tid] = tot;
    __syncthreads();
    for (int s = 128; s > 0; s >>= 1) { if (tid < s) sred[tid] += sred[tid + s]; __syncthreads(); }
    if (tid == 0) stot = fmaxf(sqrtf(sred[0]), 1e-12f);
    __syncthreads();
    for (int idx = tid; idx < ROW; idx += 256) orow[idx] /= stot;
}

// ============ launcher ============
extern "C" void kernel_launch(void* const* d_in, const int* in_sizes, int n_in,
                              void* d_out, int out_size)
{
    (void)in_sizes; (void)n_in; (void)out_size;
    const float* x    = (const float*)d_in[0];
    const float* t    = (const float*)d_in[1];
    const float* Wc1  = (const float*)d_in[2];
    const float* bc1  = (const float*)d_in[3];
    const float* Wc2  = (const float*)d_in[4];
    const float* bc2  = (const float*)d_in[5];
    const float* Ws1  = (const float*)d_in[6];
    const float* bs1  = (const float*)d_in[7];
    const float* Ws2  = (const float*)d_in[8];
    const float* bs2  = (const float*)d_in[9];
    const float* Wt1  = (const float*)d_in[10];
    const float* bt1  = (const float*)d_in[11];
    const float* Wt2  = (const float*)d_in[12];
    const float* bt2  = (const float*)d_in[13];
    const float* dust = (const float*)d_in[14];
    const float* ba   = (const float*)d_in[15];
    const float* bbp  = (const float*)d_in[16];
    const float* bp   = (const float*)d_in[17];
    float* out = (float*)d_out;

    __half *gx, *gh, *gf, *fnj, *fnk, *gPt;
    __half *wAh, *wAl, *wch, *wcl, *wsh, *wsl;
    float *pp, *pbw, *pagg, *pv, *pbA;
    cudaGetSymbolAddress((void**)&gx, g_x);
    cudaGetSymbolAddress((void**)&gh, g_h);
    cudaGetSymbolAddress((void**)&gf, g_f);
    cudaGetSymbolAddress((void**)&fnj, g_fnj); cudaGetSymbolAddress((void**)&fnk, g_fnk);
    cudaGetSymbolAddress((void**)&gPt, g_Pt);
    cudaGetSymbolAddress((void**)&wAh, g_wAh); cudaGetSymbolAddress((void**)&wAl, g_wAl);
    cudaGetSymbolAddress((void**)&wch, g_wch); cudaGetSymbolAddress((void**)&wcl, g_wcl);
    cudaGetSymbolAddress((void**)&wsh, g_wsh); cudaGetSymbolAddress((void**)&wsl, g_wsl);
    cudaGetSymbolAddress((void**)&pp, g_p);    cudaGetSymbolAddress((void**)&pbw, g_bw);
    cudaGetSymbolAddress((void**)&pagg, g_agg);
    cudaGetSymbolAddress((void**)&pv, g_v);
    cudaGetSymbolAddress((void**)&pbA, g_bA);

    cudaFuncSetAttribute(mma_gemm_kernel, cudaFuncAttributeMaxDynamicSharedMemorySize, SMEM_TOTAL);

    // combined bias for fused GEMM1 (D2D copies, graph-capturable)
    cudaMemcpyAsync(pbA, bc1, NHID * sizeof(float), cudaMemcpyDeviceToDevice);
    cudaMemcpyAsync(pbA + NHID, bs1, NHID * sizeof(float), cudaMemcpyDeviceToDevice);

    // conversions (kernels 1-5; GEMM1 is the 6th launch for ncu -s 5)
    convx_kernel<<<4096, 256>>>(x);
    convw_kernel<<<256, 256>>>(Wc1, wAh, wAl, NHID * NC);
    convw_kernel<<<256, 256>>>(Ws1, wAh + (size_t)NHID * NC, wAl + (size_t)NHID * NC, NHID * NC);
    convw_kernel<<<64, 256>>>(Wc2, wch, wcl, NL * NHID);
    convw_kernel<<<32, 256>>>(Ws2, wsh, wsl, NM * NHID);

    // fused GEMM1: h[0:512]=relu(Wc1@x+bc1), h[512:1024]=relu(Ws1@x+bs1)
    mma_gemm_kernel<<<dim3(NN/128, 1024/128, NB), 256, SMEM_TOTAL>>>(
        wAh, wAl, 0, gx, (long)NC * NN,
        NC, NN, 1024, NN, pbA, 1, 0, gh, nullptr, (long)1024 * NN, NN, nullptr, nullptr);
    // GEMM2c: f = Wc2 @ h_c + bc2
    mma_gemm_kernel<<<dim3(NN/128, 1, NB), 256, SMEM_TOTAL>>>(
        wch, wcl, 0, gh, (long)1024 * NN,
        NHID, NN, NL, NN, bc2, 0, 0, gf, nullptr, (long)NL * NN, NN, nullptr, nullptr);
    // GEMM2s: p = Ws2 @ h_s + bs2 (fp32)
    mma_gemm_kernel<<<dim3(NN/128, 1, NB), 256, SMEM_TOTAL>>>(
        wsh, wsl, 0, gh + (long)NHID * NN, (long)1024 * NN,
        NHID, NN, NM, NN, bs2, 0, 1, nullptr, pp, (long)NM * NN, NN, nullptr, nullptr);

    // token MLP
    tk1_kernel<<<(NB * NHID * 32) / 256, 256>>>(t, Wt1, bt1);
    tk2_kernel<<<(NB * NG * 32) / 256, 256>>>(Wt2, bt2);

    // burst reweighting
    colnorm_kernel<<<(NB * NN) / 256, 256>>>();
    fnt_kernel<<<dim3(NN/32, NL/32, NB), dim3(32, 8)>>>();
    cudaMemsetAsync(pbw, 0, (size_t)NB * NN * sizeof(float));
    mma_gemm_kernel<<<dim3(NN/128, NN/128, NB), 256, SMEM_TOTAL>>>(
        fnj, nullptr, (long)NN * NL, fnk, (long)NL * NN,
        NL, NN, NN, NN, nullptr, 0, 2, nullptr, nullptr, 0, 0, ba, bbp);

    // Sinkhorn
    cudaMemsetAsync(pv, 0, (size_t)NB * NN * sizeof(float));
    for (int it = 0; it < 3; it++) {
        sk_u_kernel<<<(NB * (NM + 1) * 32 + 255) / 256, 256>>>(dust);
        sk_v_kernel<<<NB * 4, 256>>>(dust);
    }
    cterm_kernel<<<(NB * NN) / 256, 256>>>(bp);
    pfinal_kernel<<<(NB * NM * NN) / 256, 256>>>();

    // agg: agg[l][m] = sum_n f[l][n] * Pt[n][m] (single-pass fp16)
    mma_gemm_kernel<<<dim3(1, 1, NB), 256, SMEM_TOTAL>>>(
        gf, nullptr, (long)NL * NN, gPt, (long)NN * NM,
        NN, NM, NL, NM, nullptr, 0, 1, nullptr, pagg, (long)NL * NM, NM, nullptr, nullptr);

    final_kernel<<<NB, 256>>>(out);
}

// round 8
// speedup vs baseline: 2.5510x; 1.5276x over previous
#include <cuda_runtime.h>
#include <cuda_fp16.h>
#include <math.h>
#include <stdint.h>

#define NB 32
#define NC 1536
#define NN 1024
#define NHID 512
#define NL 128
#define NM 64
#define NG 256

// ---- smem tile geometry (fp16) ----
#define APAD 40
#define BPAD 136
#define A_BYTES (128 * APAD * 2)            // 10240
#define B_BYTES (32 * BPAD * 2)             // 8704
#define STAGE_BYTES (2 * A_BYTES + B_BYTES) // 29184
#define SMEM_TOTAL (2 * STAGE_BYTES)        // 58368

// ---- scratch ----
__device__ __half g_x  [(size_t)NB * NC * NN];
__device__ __half g_h  [(size_t)NB * 1024 * NN];        // rows 0-511: h_c, 512-1023: h_s
__device__ __half g_f  [(size_t)NB * NL * NN];
__device__ __half g_fnj[(size_t)NB * NN * NL];
__device__ __half g_fnk[(size_t)NB * NL * NN];
__device__ float  g_p  [(size_t)NB * NM * NN];
__device__ __half g_Pt [(size_t)NB * NN * NM];
__device__ __half g_wAh[1024 * NC];                     // fused [Wc1;Ws1] hi only
__device__ float  g_bA [1024];
__device__ __half g_wch[NL * NHID], g_wcl[NL * NHID];
__device__ __half g_wsh[NM * NHID], g_wsl[NM * NHID];
__device__ float g_u[NB * (NM + 1)];
__device__ float g_v[NB * NN];
__device__ float g_norms[NB * NN];
__device__ float g_bw[NB * NN];
__device__ float g_agg[NB * NL * NM];
__device__ float g_tht[NB * NHID];
__device__ float g_tk[NB * NG];

__device__ __forceinline__ void split2h(float v, __half& h, __half& l) {
    h = __float2half_rn(v);
    l = __float2half_rn(v - __half2float(h));
}
__device__ __forceinline__ uint32_t smem_u32(const void* p) {
    uint32_t a;
    asm("{ .reg .u64 t; cvta.to.shared.u64 t, %1; cvt.u32.u64 %0, t; }" : "=r"(a) : "l"(p));
    return a;
}
__device__ __forceinline__ void cp16(uint32_t d, const void* s, bool pred) {
    int sz = pred ? 16 : 0;
    asm volatile("cp.async.cg.shared.global [%0], [%1], 16, %2;"
                 :: "r"(d), "l"(s), "r"(sz) : "memory");
}
#define CP_COMMIT() asm volatile("cp.async.commit_group;" ::: "memory")
#define CP_WAIT0()  asm volatile("cp.async.wait_group 0;" ::: "memory")

__device__ __forceinline__ void ldmx4(uint32_t* r, uint32_t a) {
    asm volatile("ldmatrix.sync.aligned.m8n8.x4.shared.b16 {%0,%1,%2,%3}, [%4];"
        : "=r"(r[0]), "=r"(r[1]), "=r"(r[2]), "=r"(r[3]) : "r"(a));
}
__device__ __forceinline__ void ldmx2t(uint32_t* r, uint32_t a) {
    asm volatile("ldmatrix.sync.aligned.m8n8.x2.trans.shared.b16 {%0,%1}, [%2];"
        : "=r"(r[0]), "=r"(r[1]) : "r"(a));
}
__device__ __forceinline__ void mma16816(float* d, const uint32_t* a, const uint32_t* b) {
    asm volatile("mma.sync.aligned.m16n8k16.row.col.f32.f16.f16.f32 "
        "{%0,%1,%2,%3}, {%4,%5,%6,%7}, {%8,%9}, {%0,%1,%2,%3};"
        : "+f"(d[0]), "+f"(d[1]), "+f"(d[2]), "+f"(d[3])
        : "r"(a[0]), "r"(a[1]), "r"(a[2]), "r"(a[3]), "r"(b[0]), "r"(b[1]));
}

// ================= GEMM tile (templated M-extent), device function =================
// MI=4: 128-row tile; MI=2: 64-row tile. Mainloop identical to the validated R7 version.
template<int MI>
__device__ void gemm_tile(
    int bx, int by, int bz,
    const __half* __restrict__ Ah, const __half* __restrict__ Al, long sA,
    const __half* __restrict__ B, long sB,
    int K, int ldB, int Mvalid, int Nvalid,
    const float* __restrict__ bias, int relu, int mode,
    __half* __restrict__ oh, float* __restrict__ of, long sO, int ldo,
    const float* __restrict__ pa, const float* __restrict__ pb)
{
    extern __shared__ char smem[];
    const uint32_t su = smem_u32(smem);
    const int tid = threadIdx.x, lane = tid & 31, wid = tid >> 5;
    const int wm = wid >> 2, wn = wid & 3;
    const int n0 = bx * 128, m0 = by * (MI * 32);
    const bool x2 = (Al != nullptr);

    const __half* A_h = Ah + (long)bz * sA + (long)m0 * K;
    const __half* A_l = x2 ? Al + (long)bz * sA + (long)m0 * K : A_h;
    const __half* B_p = B + (long)bz * sB;
    const int mMax = (Mvalid - m0 < MI * 32) ? (Mvalid - m0) : MI * 32;

    float acc[MI][4][4];
#pragma unroll
    for (int i = 0; i < MI; i++)
#pragma unroll
        for (int j = 0; j < 4; j++)
#pragma unroll
            for (int q = 0; q < 4; q++) acc[i][j][q] = 0.f;

    const int nc = K >> 5;

    auto prefetch = [&](int c, int st) {
        uint32_t sa = su + st * STAGE_BYTES;
        long kb = (long)c * 32;
#pragma unroll
        for (int i = 0; i < MI / 2; i++) {
            int idx = tid + i * 256;
            int row = idx >> 2, cc = idx & 3;
            uint32_t doff = sa + row * (APAD * 2) + cc * 16;
            bool p = row < mMax;
            cp16(doff, A_h + (long)row * K + kb + cc * 8, p);
            if (x2) cp16(doff + A_BYTES, A_l + (long)row * K + kb + cc * 8, p);
        }
#pragma unroll
        for (int i = 0; i < 2; i++) {
            int idx = tid + i * 256;
            int row = idx >> 4, cc = idx & 15;
            uint32_t doff = sa + 2 * A_BYTES + row * (BPAD * 2) + cc * 16;
            bool p = (n0 + cc * 8) < Nvalid;
            cp16(doff, B_p + (kb + row) * (long)ldB + n0 + cc * 8, p);
        }
    };

    prefetch(0, 0);
    CP_COMMIT();

    for (int c = 0; c < nc; c++) {
        CP_WAIT0();
        __syncthreads();
        if (c + 1 < nc) { prefetch(c + 1, (c + 1) & 1); CP_COMMIT(); }

        uint32_t sa = su + (c & 1) * STAGE_BYTES;
#pragma unroll
        for (int kk = 0; kk < 2; kk++) {
            uint32_t afh[MI][4], afl[MI][4];
#pragma unroll
            for (int mi = 0; mi < MI; mi++) {
                uint32_t ad = sa + ((wm * (MI * 16) + mi * 16 + (lane & 15)) * APAD
                                    + kk * 16 + (lane >> 4) * 8) * 2;
                ldmx4(afh[mi], ad);
                if (x2) ldmx4(afl[mi], ad + A_BYTES);
            }
            uint32_t bf[4][2];
#pragma unroll
            for (int ni = 0; ni < 4; ni++) {
                uint32_t bd = sa + 2 * A_BYTES
                            + (kk * 16 + (lane & 15)) * (BPAD * 2)
                            + (wn * 32 + ni * 8) * 2;
                ldmx2t(bf[ni], bd);
            }
#pragma unroll
            for (int ni = 0; ni < 4; ni++)
#pragma unroll
                for (int mi = 0; mi < MI; mi++)
                    mma16816(acc[mi][ni], afh[mi], bf[ni]);
            if (x2) {
#pragma unroll
                for (int ni = 0; ni < 4; ni++)
#pragma unroll
                    for (int mi = 0; mi < MI; mi++)
                        mma16816(acc[mi][ni], afl[mi], bf[ni]);
            }
        }
    }

    const int g = lane >> 2, tq = lane & 3;
    if (mode == 2) {
        const float a = *pa, bb = *pb;
        const bool fast = (fabsf(a) + fabsf(bb)) <= 1.0f;
#pragma unroll
        for (int mi = 0; mi < MI; mi++) {
            float r0 = 0.f, r1 = 0.f;
#pragma unroll
            for (int ni = 0; ni < 4; ni++) {
#pragma unroll
                for (int q = 0; q < 4; q++) {
                    float z = a * acc[mi][ni][q] + bb;
                    float s;
                    if (fast) {
                        float tt = 0.5f * z, t2 = tt * tt;
                        float th = tt * (1.f + t2 * (-0.3333333333f
                                   + t2 * (0.1333333333f - t2 * 0.05396825397f)));
                        s = 0.5f + 0.5f * th;
                    } else {
                        s = 1.f / (1.f + __expf(-z));
                    }
                    if (q < 2) r0 += s; else r1 += s;
                }
            }
            r0 += __shfl_xor_sync(0xffffffffu, r0, 1);
            r0 += __shfl_xor_sync(0xffffffffu, r0, 2);
            r1 += __shfl_xor_sync(0xffffffffu, r1, 1);
            r1 += __shfl_xor_sync(0xffffffffu, r1, 2);
            if (tq == 0) {
                int j = m0 + wm * (MI * 16) + mi * 16 + g;
                atomicAdd(&g_bw[bz * NN + j], r0);
                atomicAdd(&g_bw[bz * NN + j + 8], r1);
            }
        }
        return;
    }

#pragma unroll
    for (int mi = 0; mi < MI; mi++) {
        int r0 = m0 + wm * (MI * 16) + mi * 16 + g;
        int r1 = r0 + 8;
        float b0v = (bias && r0 < Mvalid) ? bias[r0] : 0.f;
        float b1v = (bias && r1 < Mvalid) ? bias[r1] : 0.f;
#pragma unroll
        for (int ni = 0; ni < 4; ni++) {
            int col = n0 + wn * 32 + ni * 8 + tq * 2;
            if (col >= Nvalid) continue;
            float v00 = acc[mi][ni][0] + b0v, v01 = acc[mi][ni][1] + b0v;
            float v10 = acc[mi][ni][2] + b1v, v11 = acc[mi][ni][3] + b1v;
            if (relu) {
                v00 = fmaxf(v00, 0.f); v01 = fmaxf(v01, 0.f);
                v10 = fmaxf(v10, 0.f); v11 = fmaxf(v11, 0.f);
            }
            if (mode == 0) {
                if (r0 < Mvalid) {
                    long off = (long)bz * sO + (long)r0 * ldo + col;
                    __half h0 = __float2half_rn(v00), h1 = __float2half_rn(v01);
                    *reinterpret_cast<uint32_t*>(oh + off) =
                        (uint32_t)__half_as_ushort(h0) | ((uint32_t)__half_as_ushort(h1) << 16);
                }
                if (r1 < Mvalid) {
                    long off = (long)bz * sO + (long)r1 * ldo + col;
                    __half h0 = __float2half_rn(v10), h1 = __float2half_rn(v11);
                    *reinterpret_cast<uint32_t*>(oh + off) =
                        (uint32_t)__half_as_ushort(h0) | ((uint32_t)__half_as_ushort(h1) << 16);
                }
            } else {
                if (r0 < Mvalid)
                    *reinterpret_cast<float2*>(of + (long)bz * sO + (long)r0 * ldo + col) =
                        make_float2(v00, v01);
                if (r1 < Mvalid)
                    *reinterpret_cast<float2*>(of + (long)bz * sO + (long)r1 * ldo + col) =
                        make_float2(v10, v11);
            }
        }
    }
}

// ================= small device bodies =================
__device__ void tk1_body(int bid, const float* __restrict__ t,
                         const float* __restrict__ W, const float* __restrict__ bias)
{
    int gw = (bid * 256 + threadIdx.x) >> 5;         // < NB*NHID = 16384
    int lane = threadIdx.x & 31;
    int o = gw % NHID, b = gw / NHID;
    const float* tr = t + (long)b * NC;
    const float* wr = W + (long)o * NC;
    float s = 0.f;
    for (int k = lane; k < NC; k += 32) s = fmaf(tr[k], wr[k], s);
#pragma unroll
    for (int off = 16; off > 0; off >>= 1) s += __shfl_xor_sync(0xffffffffu, s, off);
    if (lane == 0) g_tht[b * NHID + o] = fmaxf(s + bias[o], 0.f);
}
__device__ void tk2_body(int bid, const float* __restrict__ W, const float* __restrict__ bias)
{
    int gw = (bid * 256 + threadIdx.x) >> 5;         // < NB*NG = 8192
    int lane = threadIdx.x & 31;
    int o = gw % NG, b = gw / NG;
    const float* hr = g_tht + (long)b * NHID;
    const float* wr = W + (long)o * NHID;
    float s = 0.f;
    for (int k = lane; k < NHID; k += 32) s = fmaf(hr[k], wr[k], s);
#pragma unroll
    for (int off = 16; off > 0; off >>= 1) s += __shfl_xor_sync(0xffffffffu, s, off);
    if (lane == 0) g_tk[b * NG + o] = s + bias[o];
}
__device__ void sk_u_body(int bid, const float* __restrict__ pdust)
{
    const float NORMC = -logf((float)(NM + NN));
    const float LOGN = logf((float)NN);
    int gw = (bid * 256 + threadIdx.x) >> 5;         // < NB*65 = 2080
    int lane = threadIdx.x & 31;
    int i = gw % (NM + 1), b = gw / (NM + 1);

    const float4* v4 = reinterpret_cast<const float4*>(g_v + b * NN);
    float xs[32];
    if (i < NM) {
        const float4* p4 = reinterpret_cast<const float4*>(g_p + ((long)b * NM + i) * NN);
#pragma unroll
        for (int w = 0; w < 8; w++) {
            float4 pv = p4[w * 32 + lane];
            float4 vv = v4[w * 32 + lane];
            xs[4*w]   = pv.x + vv.x; xs[4*w+1] = pv.y + vv.y;
            xs[4*w+2] = pv.z + vv.z; xs[4*w+3] = pv.w + vv.w;
        }
    } else {
        float dust = *pdust;
#pragma unroll
        for (int w = 0; w < 8; w++) {
            float4 vv = v4[w * 32 + lane];
            xs[4*w]   = dust + vv.x; xs[4*w+1] = dust + vv.y;
            xs[4*w+2] = dust + vv.z; xs[4*w+3] = dust + vv.w;
        }
    }
    float mx = xs[0];
#pragma unroll
    for (int q = 1; q < 32; q++) mx = fmaxf(mx, xs[q]);
#pragma unroll
    for (int off = 16; off > 0; off >>= 1) mx = fmaxf(mx, __shfl_xor_sync(0xffffffffu, mx, off));
    float s = 0.f;
#pragma unroll
    for (int q = 0; q < 32; q++) s += __expf(xs[q] - mx);
#pragma unroll
    for (int off = 16; off > 0; off >>= 1) s += __shfl_xor_sync(0xffffffffu, s, off);
    if (lane == 0)
        g_u[b * (NM + 1) + i] = ((i < NM) ? NORMC : (LOGN + NORMC)) - (mx + __logf(s));
}
__device__ void sk_v_body(int bid, const float* __restrict__ pdust)
{
    const float NORMC = -logf((float)(NM + NN));
    __shared__ float su[NM + 1];
    int b = bid >> 2, q = bid & 3;
    int tid = threadIdx.x;
    if (tid <= NM) su[tid] = g_u[b * (NM + 1) + tid];
    __syncthreads();
    int j = q * 256 + tid;
    const float* pb = g_p + (long)b * NM * NN + j;
    float mx = *pdust + su[NM];
    float s = 1.f;
#pragma unroll 8
    for (int i = 0; i < NM; i++) {
        float x = pb[(long)i * NN] + su[i];
        if (x > mx) { s = s * __expf(mx - x) + 1.f; mx = x; }
        else        { s += __expf(x - mx); }
    }
    g_v[b * NN + j] = NORMC - (mx + __logf(s));
}
__device__ void convw_body(int bid, int nblk, const float* __restrict__ s,
                           __half* __restrict__ dh, __half* __restrict__ dl, int count)
{
    for (int i = bid * 256 + threadIdx.x; i < count; i += nblk * 256) {
        if (dl) { __half h, l; split2h(s[i], h, l); dh[i] = h; dl[i] = l; }
        else    { dh[i] = __float2half_rn(s[i]); }
    }
}

// ================= merged global kernels =================
__global__ void mega_convert(const float* __restrict__ x,
                             const float* __restrict__ Wc1, const float* __restrict__ Ws1,
                             const float* __restrict__ Wc2, const float* __restrict__ Ws2,
                             const float* __restrict__ bc1, const float* __restrict__ bs1)
{
    int id = blockIdx.x;
    if (id < 4096) {
        long i = (long)id * 256 + threadIdx.x;
        const long total = (long)NB * NC * NN / 4;
        for (; i < total; i += 4096L * 256) {
            float4 v = reinterpret_cast<const float4*>(x)[i];
            __half2 a = __floats2half2_rn(v.x, v.y);
            __half2 b = __floats2half2_rn(v.z, v.w);
            reinterpret_cast<uint2*>(g_x)[i] =
                make_uint2(*reinterpret_cast<uint32_t*>(&a), *reinterpret_cast<uint32_t*>(&b));
        }
    } else if (id < 4224) {
        convw_body(id - 4096, 128, Wc1, g_wAh, nullptr, NHID * NC);
    } else if (id < 4352) {
        convw_body(id - 4224, 128, Ws1, g_wAh + (size_t)NHID * NC, nullptr, NHID * NC);
    } else if (id < 4416) {
        convw_body(id - 4352, 64, Wc2, g_wch, g_wcl, NL * NHID);
    } else if (id < 4448) {
        convw_body(id - 4416, 32, Ws2, g_wsh, g_wsl, NM * NHID);
    } else {
        for (int i = threadIdx.x; i < NHID; i += 256) {
            g_bA[i] = bc1[i];
            g_bA[NHID + i] = bs1[i];
        }
    }
}

__global__ void __launch_bounds__(256, 2) k_gemm1(
    const float* __restrict__ t, const float* __restrict__ Wt1, const float* __restrict__ bt1)
{
    int id = blockIdx.x;
    if (id < 2048) {
        gemm_tile<4>(id & 7, (id >> 3) & 7, id >> 6,
                     g_wAh, nullptr, 0, g_x, (long)NC * NN,
                     NC, NN, 1024, NN, g_bA, 1, 0,
                     g_h, nullptr, (long)1024 * NN, NN, nullptr, nullptr);
    } else {
        tk1_body(id - 2048, t, Wt1, bt1);
    }
}

__global__ void __launch_bounds__(256, 2) k_gemm2(
    const float* __restrict__ bc2, const float* __restrict__ bs2,
    const float* __restrict__ Wt2, const float* __restrict__ bt2)
{
    int id = blockIdx.x;
    if (id < 256) {
        gemm_tile<4>(id & 7, 0, id >> 3,
                     g_wch, g_wcl, 0, g_h, (long)1024 * NN,
                     NHID, NN, NL, NN, bc2, 0, 0,
                     g_f, nullptr, (long)NL * NN, NN, nullptr, nullptr);
    } else if (id < 512) {
        int q = id - 256;
        gemm_tile<2>(q & 7, 0, q >> 3,
                     g_wsh, g_wsl, 0, g_h + (long)NHID * NN, (long)1024 * NN,
                     NHID, NN, NM, NN, bs2, 0, 1,
                     nullptr, g_p, (long)NM * NN, NN, nullptr, nullptr);
    } else {
        tk2_body(id - 512, Wt2, bt2);
    }
}

// colnorm + zero bw + zero v
__global__ void mega_misc()
{
    int id = blockIdx.x;
    if (id < 128) {
        int idx = id * 256 + threadIdx.x;
        int b = idx >> 10, j = idx & (NN - 1);
        long base = (long)b * NL * NN + j;
        float s = 0.f;
        for (int l = 0; l < NL; l++) {
            float v = __half2float(g_f[base + (long)l * NN]);
            s = fmaf(v, v, s);
        }
        g_norms[idx] = fmaxf(sqrtf(s), 1e-12f);
    } else if (id < 256) {
        g_bw[(id - 128) * 256 + threadIdx.x] = 0.f;
    } else if (id < 384) {
        g_v[(id - 256) * 256 + threadIdx.x] = 0.f;
    }
}

__global__ void fnt_kernel()
{
    __shared__ float tile[32][33];
    int b = blockIdx.z, l0 = blockIdx.y * 32, n0 = blockIdx.x * 32;
    int tx = threadIdx.x, ty = threadIdx.y;
    long fb = (long)b * NL * NN;
#pragma unroll
    for (int i = 0; i < 4; i++) {
        int l = l0 + ty + i * 8;
        tile[ty + i * 8][tx] = __half2float(g_f[fb + (long)l * NN + n0 + tx]);
    }
    __syncthreads();
    float nv = g_norms[b * NN + n0 + tx];
#pragma unroll
    for (int i = 0; i < 4; i++) {
        int l = l0 + ty + i * 8;
        g_fnk[fb + (long)l * NN + n0 + tx] = __float2half_rn(tile[ty + i * 8][tx] / nv);
    }
#pragma unroll
    for (int i = 0; i < 4; i++) {
        int r = ty + i * 8;
        float nv2 = g_norms[b * NN + n0 + r];
        g_fnj[((long)b * NN + n0 + r) * NL + l0 + tx] =
            __float2half_rn(tile[tx][r] / nv2);
    }
}

// Sinkhorn stage merged with a slice of the burst Gram GEMM
__global__ void __launch_bounds__(256, 2) k_burst_sk(
    int sliceStart, int nSlice, int skN, int phase,
    const float* __restrict__ pdust,
    const float* __restrict__ pa, const float* __restrict__ pb)
{
    int id = blockIdx.x;
    if (id < skN) {
        if (phase == 0) sk_u_body(id, pdust);
        else            sk_v_body(id, pdust);
    } else {
        int flat = sliceStart + (id - skN);
        gemm_tile<4>(flat & 7, (flat >> 3) & 7, flat >> 6,
                     g_fnj, nullptr, (long)NN * NL, g_fnk, (long)NL * NN,
                     NL, NN, NN, NN, nullptr, 0, 2,
                     nullptr, nullptr, 0, 0, pa, pb);
    }
}

__global__ void cterm_kernel(const float* __restrict__ pbp)
{
    const float NORMC = -logf((float)(NM + NN));
    int idx = blockIdx.x * blockDim.x + threadIdx.x;
    if (idx >= NB * NN) return;
    g_v[idx] = g_v[idx] - NORMC - (*pbp) * __logf(g_bw[idx]);
}

__global__ void pfinal_kernel()
{
    long idx = (long)blockIdx.x * blockDim.x + threadIdx.x;
    int b = (int)(idx >> 16);
    int i = (int)((idx >> 10) & 63);
    int j = (int)(idx & 1023);
    float val = __expf(g_p[idx] + g_u[b * (NM + 1) + i] + g_v[b * NN + j]);
    g_Pt[((long)b * NN + j) * NM + i] = __float2half_rn(val);
}

__global__ void __launch_bounds__(256, 2) k_agg()
{
    gemm_tile<4>(0, 0, blockIdx.x,
                 g_f, nullptr, (long)NL * NN, g_Pt, (long)NN * NM,
                 NN, NM, NL, NM, nullptr, 0, 1,
                 nullptr, g_agg, (long)NL * NM, NM, nullptr, nullptr);
}

__global__ void final_kernel(float* __restrict__ out)
{
    const int b = blockIdx.x, tid = threadIdx.x;
    __shared__ float sred[256];
    __shared__ float cnorm[NM];
    __shared__ float stk, stot;

    float v = g_tk[b * NG + tid];
    sred[tid] = v * v;
    __syncthreads();
    for (int s = 128; s > 0; s >>= 1) { if (tid < s) sred[tid] += sred[tid + s]; __syncthreads(); }
    if (tid == 0) stk = fmaxf(sqrtf(sred[0]), 1e-12f);
    __syncthreads();
    {
        int m = tid & 63, part = tid >> 6;
        const float* ab = g_agg + (long)b * NL * NM;
        float s = 0.f;
        for (int l = part * 32; l < part * 32 + 32; l++) {
            float x = ab[(long)l * NM + m];
            s = fmaf(x, x, s);
        }
        sred[tid] = s;
        __syncthreads();
        if (tid < 64)
            cnorm[tid] = fmaxf(sqrtf(sred[tid] + sred[tid+64] + sred[tid+128] + sred[tid+192]), 1e-12f);
        __syncthreads();
    }
    const int ROW = NG + NL * NM;
    float* orow = out + (long)b * ROW;
    float tot = 0.f;
    for (int idx = tid; idx < ROW; idx += 256) {
        float val;
        if (idx < NG) val = g_tk[b * NG + idx] / stk;
        else {
            int r = idx - NG;
            val = g_agg[((long)b * NL + (r >> 6)) * NM + (r & 63)] / cnorm[r & 63];
        }
        orow[idx] = val;
        tot += val * val;
    }
    sred[tid] = tot;
    __syncthreads();
    for (int s = 128; s > 0; s >>= 1) { if (tid < s) sred[tid] += sred[tid + s]; __syncthreads(); }
    if (tid == 0) stot = fmaxf(sqrtf(sred[0]), 1e-12f);
    __syncthreads();
    for (int idx = tid; idx < ROW; idx += 256) orow[idx] /= stot;
}

// ============ launcher ============
extern "C" void kernel_launch(void* const* d_in, const int* in_sizes, int n_in,
                              void* d_out, int out_size)
{
    (void)in_sizes; (void)n_in; (void)out_size;
    const float* x    = (const float*)d_in[0];
    const float* t    = (const float*)d_in[1];
    const float* Wc1  = (const float*)d_in[2];
    const float* bc1  = (const float*)d_in[3];
    const float* Wc2  = (const float*)d_in[4];
    const float* bc2  = (const float*)d_in[5];
    const float* Ws1  = (const float*)d_in[6];
    const float* bs1  = (const float*)d_in[7];
    const float* Ws2  = (const float*)d_in[8];
    const float* bs2  = (const float*)d_in[9];
    const float* Wt1  = (const float*)d_in[10];
    const float* bt1  = (const float*)d_in[11];
    const float* Wt2  = (const float*)d_in[12];
    const float* bt2  = (const float*)d_in[13];
    const float* dust = (const float*)d_in[14];
    const float* ba   = (const float*)d_in[15];
    const float* bbp  = (const float*)d_in[16];
    const float* bp   = (const float*)d_in[17];
    float* out = (float*)d_out;

    cudaFuncSetAttribute(k_gemm1,    cudaFuncAttributeMaxDynamicSharedMemorySize, SMEM_TOTAL);
    cudaFuncSetAttribute(k_gemm2,    cudaFuncAttributeMaxDynamicSharedMemorySize, SMEM_TOTAL);
    cudaFuncSetAttribute(k_burst_sk, cudaFuncAttributeMaxDynamicSharedMemorySize, SMEM_TOTAL);
    cudaFuncSetAttribute(k_agg,      cudaFuncAttributeMaxDynamicSharedMemorySize, SMEM_TOTAL);

    // 1: all conversions + bias concat
    mega_convert<<<4449, 256>>>(x, Wc1, Ws1, Wc2, Ws2, bc1, bs1);

    // 2: fused GEMM1 (single-pass W) + token MLP layer 1
    k_gemm1<<<4096, 256, SMEM_TOTAL>>>(t, Wt1, bt1);

    // 3: GEMM2c + GEMM2s (MI=2) + token MLP layer 2
    k_gemm2<<<1536, 256, SMEM_TOTAL>>>(bc2, bs2, Wt2, bt2);

    // 4: colnorm + zero(bw) + zero(v)
    mega_misc<<<384, 256>>>();

    // 5: normalized-f layouts
    fnt_kernel<<<dim3(NN/32, NL/32, NB), dim3(32, 8)>>>();

    // 6-11: burst Gram slices overlapped with Sinkhorn stages
    {
        const int sizes[6] = {342, 342, 342, 342, 340, 340};
        int start = 0;
        for (int it = 0; it < 3; it++) {
            k_burst_sk<<<260 + sizes[2*it], 256, SMEM_TOTAL>>>(
                start, sizes[2*it], 260, 0, dust, ba, bbp);
            start += sizes[2*it];
            k_burst_sk<<<128 + sizes[2*it+1], 256, SMEM_TOTAL>>>(
                start, sizes[2*it+1], 128, 1, dust, ba, bbp);
            start += sizes[2*it+1];
        }
    }

    // 12-13: column term + transport plan
    cterm_kernel<<<(NB * NN) / 256, 256>>>(bp);
    pfinal_kernel<<<(NB * NM * NN) / 256, 256>>>();

    // 14-15: aggregation + final normalize
    k_agg<<<NB, 256, SMEM_TOTAL>>>();
    final_kernel<<<NB, 256>>>(out);
}